// round 10
// baseline (speedup 1.0000x reference)
#include <cuda_runtime.h>
#include <cuda_bf16.h>
#include <stdint.h>
#include <math.h>

#define BB  2
#define CIN 512
#define CC  256
#define HH  48
#define WW  48
#define HWW 2304
#define LL  2304
#define DI  512
#define BL  (BB*LL)          /* 4608 tokens */
#define BNF 0.9999950000374997f

typedef __nv_bfloat16 bf16;

// ------------------------- static scratch (no allocs) -------------------------
// fp32 token-major activations
__device__ __align__(256) float g_xred[BL*CC];
__device__ __align__(256) float g_p[BL*CC];
__device__ __align__(256) float g_featloc[BL*CC];
__device__ __align__(256) float g_featglob[BL*CC];
__device__ __align__(256) float g_xz[BL*2*DI];
__device__ __align__(256) float g_xm[4*BL*DI];
__device__ __align__(256) float g_projm[4*BL*48];
__device__ __align__(256) float g_dtb[4*BL*DI];
__device__ __align__(256) __nv_bfloat16 g_y[4*BL*DI];
// bf16 split activations
__device__ __align__(256) bf16 g_xthi[BL*CIN],  g_xtlo[BL*CIN];
__device__ __align__(256) bf16 g_xrhi[BL*CC],   g_xrlo[BL*CC];
__device__ __align__(256) bf16 g_xnhi[BL*CC],   g_xnlo[BL*CC];
__device__ __align__(256) bf16 g_hvhi[BL*CC],   g_hvlo[BL*CC];
__device__ __align__(256) bf16 g_yshi[BL*DI],   g_yslo[BL*DI];
// bf16 split weights
__device__ __align__(256) bf16 g_rwhi[CC*CIN],  g_rwlo[CC*CIN];
__device__ __align__(256) bf16 g_pwhi[CC*CC],   g_pwlo[CC*CC];
__device__ __align__(256) bf16 g_fwhi[CC*CC],   g_fwlo[CC*CC];
__device__ __align__(256) bf16 g_iwhi[2*DI*CC], g_iwlo[2*DI*CC];
__device__ __align__(256) bf16 g_owhi[CC*DI],   g_owlo[CC*DI];
// misc
__device__ __align__(256) float g_dtwT[16*DI];
__device__ __align__(256) float g_xpw[48*DI];
__device__ __align__(256) int   g_map[4*LL];
__device__ __align__(256) float g_msum[BB*36*CC];
__device__ __align__(256) float g_sv[BB*CC];
__device__ __align__(256) float g_wv[BB*2*CC];

__device__ __forceinline__ int seq_map(int dir, int t) {
    if (dir == 0) return t;
    if (dir == 1) return LL - 1 - t;
    int u = (dir == 2) ? t : (LL - 1 - t);
    int h = u % HH, w = u / HH;
    return h * WW + w;
}
__device__ __forceinline__ float silu_f(float x) { return x / (1.f + __expf(-x)); }
__device__ __forceinline__ void split_bf(float v, bf16& h, bf16& l) {
    h = __float2bfloat16(v);
    l = __float2bfloat16(v - __bfloat162float(h));
}

// ------------------ one-time prep: weight splits, maps, transposes ------------
__global__ void init_misc_k(const float* __restrict__ dtw, const float* __restrict__ xpw,
                            const float* __restrict__ rw, const float* __restrict__ pw,
                            const float* __restrict__ fw, const float* __restrict__ iw,
                            const float* __restrict__ ow)
{
    int i = blockIdx.x * 256 + threadIdx.x;
    if (i < 16 * DI) {
        int dd = i >> 4, r = i & 15;
        g_dtwT[r * DI + dd] = dtw[i];
    }
    if (i < 4 * LL) g_map[i] = seq_map(i / LL, i % LL);
    if (i < 48 * DI) {
        int j = i >> 9, k = i & 511;
        int src = (j < 16) ? j
                : (((j - 16) & 1) ? 32 + ((j - 16) >> 1) : 16 + ((j - 16) >> 1));
        g_xpw[i] = xpw[src * DI + k];
    }
    // weight splits (cumulative ranges)
    int o = i;
    if (o < CC*CIN) { split_bf(rw[o], g_rwhi[o], g_rwlo[o]); return; }
    o -= CC*CIN;
    if (o < CC*CC)  { split_bf(pw[o], g_pwhi[o], g_pwlo[o]); return; }
    o -= CC*CC;
    if (o < CC*CC)  { split_bf(fw[o], g_fwhi[o], g_fwlo[o]); return; }
    o -= CC*CC;
    if (o < 2*DI*CC){ split_bf(iw[o], g_iwhi[o], g_iwlo[o]); return; }
    o -= 2*DI*CC;
    if (o < CC*DI)  { split_bf(ow[o], g_owhi[o], g_owlo[o]); return; }
}

// ---------- input transpose: x[b][cin][hw] -> xT hi/lo [(b*HW+l)][cin] --------
__global__ void trans_in_k(const float* __restrict__ x)
{
    __shared__ float tile[32][33];
    int b = blockIdx.z;
    int l0 = blockIdx.x * 32, c0 = blockIdx.y * 32;
    int tx = threadIdx.x, ty = threadIdx.y;      // (32,8)
#pragma unroll
    for (int i = 0; i < 4; i++)
        tile[ty + i*8][tx] = x[((long long)b*CIN + c0 + ty + i*8) * HWW + l0 + tx];
    __syncthreads();
#pragma unroll
    for (int i = 0; i < 4; i++) {
        long long o = ((long long)b*HWW + l0 + ty + i*8) * CIN + c0 + tx;
        bf16 h, l;
        split_bf(tile[tx][ty + i*8], h, l);
        g_xthi[o] = h; g_xtlo[o] = l;
    }
}

// ======================= bf16 3-pass tensor-core GEMM =========================
// C[m][n] = f(sum_k A[m][k]*B[n][k]) with A = Ahi+Alo, B = Bhi+Blo,
// computed as Ah*Bh + Al*Bh + Ah*Bl. Block 128x64, 4 warps, warp tile 64x32.
// MODE: 0 plain fp32; 1 BN+ReLU fp32+hi/lo; 2 BN+ReLU fp32; 3 +bias fp32;
//       4 0.25*+extra fp32.
#define ASTR 40
__device__ __forceinline__ void mma16816(float* d, uint32_t a0, uint32_t a1,
                                         uint32_t a2, uint32_t a3,
                                         uint32_t b0, uint32_t b1)
{
    asm volatile(
        "mma.sync.aligned.m16n8k16.row.col.f32.bf16.bf16.f32 "
        "{%0,%1,%2,%3}, {%4,%5,%6,%7}, {%8,%9}, {%0,%1,%2,%3};\n"
        : "+f"(d[0]), "+f"(d[1]), "+f"(d[2]), "+f"(d[3])
        : "r"(a0), "r"(a1), "r"(a2), "r"(a3), "r"(b0), "r"(b1));
}

template<int MODE>
__global__ void __launch_bounds__(128) gemm_t3(
    const bf16* __restrict__ Ahi, const bf16* __restrict__ Alo,
    const bf16* __restrict__ Bhi, const bf16* __restrict__ Blo,
    float* __restrict__ outf, bf16* __restrict__ ohi, bf16* __restrict__ olo,
    int M, int N, int K,
    const float* __restrict__ sc, const float* __restrict__ bi,
    const float* __restrict__ extra)
{
    __shared__ bf16 As[128 * ASTR];
    __shared__ bf16 Bs[64 * ASTR];
    int tid = threadIdx.x;
    int warp = tid >> 5, lane = tid & 31;
    int gID = lane >> 2, tig = lane & 3;
    int wm = (warp >> 1) * 64, wn = (warp & 1) * 32;
    int m0 = blockIdx.y * 128, n0 = blockIdx.x * 64;

    int srow = tid >> 2;                 // 0..31
    int skc = (tid & 3) * 8;             // 0,8,16,24

    int K32 = K >> 5;
    int G = 3 * K32;

    uint4 ra[4], rb[2];
    {   // preload g=0 (pass 0: Ahi,Bhi, k=0)
#pragma unroll
        for (int i = 0; i < 4; i++)
            ra[i] = *(const uint4*)(Ahi + (long long)(m0 + srow + i*32) * K + skc);
#pragma unroll
        for (int i = 0; i < 2; i++)
            rb[i] = *(const uint4*)(Bhi + (long long)(n0 + srow + i*32) * K + skc);
    }

    float acc[4][4][4] = {};

    for (int g = 0; g < G; g++) {
#pragma unroll
        for (int i = 0; i < 4; i++)
            *(uint4*)&As[(srow + i*32) * ASTR + skc] = ra[i];
#pragma unroll
        for (int i = 0; i < 2; i++)
            *(uint4*)&Bs[(srow + i*32) * ASTR + skc] = rb[i];
        __syncthreads();
        int gn = g + 1;
        if (gn < G) {
            int pass = gn / K32;
            int kk = (gn - pass * K32) * 32;
            const bf16* Ag = (pass == 1) ? Alo : Ahi;
            const bf16* Bg = (pass == 2) ? Blo : Bhi;
#pragma unroll
            for (int i = 0; i < 4; i++)
                ra[i] = *(const uint4*)(Ag + (long long)(m0 + srow + i*32) * K + kk + skc);
#pragma unroll
            for (int i = 0; i < 2; i++)
                rb[i] = *(const uint4*)(Bg + (long long)(n0 + srow + i*32) * K + kk + skc);
        }
#pragma unroll
        for (int ks = 0; ks < 32; ks += 16) {
            uint32_t af[4][4], bfr[4][2];
#pragma unroll
            for (int mi = 0; mi < 4; mi++) {
                int r = wm + mi*16 + gID;
                af[mi][0] = *(const uint32_t*)&As[r * ASTR + ks + 2*tig];
                af[mi][1] = *(const uint32_t*)&As[(r+8) * ASTR + ks + 2*tig];
                af[mi][2] = *(const uint32_t*)&As[r * ASTR + ks + 2*tig + 8];
                af[mi][3] = *(const uint32_t*)&As[(r+8) * ASTR + ks + 2*tig + 8];
            }
#pragma unroll
            for (int nj = 0; nj < 4; nj++) {
                int r = wn + nj*8 + gID;
                bfr[nj][0] = *(const uint32_t*)&Bs[r * ASTR + ks + 2*tig];
                bfr[nj][1] = *(const uint32_t*)&Bs[r * ASTR + ks + 2*tig + 8];
            }
#pragma unroll
            for (int mi = 0; mi < 4; mi++)
#pragma unroll
                for (int nj = 0; nj < 4; nj++)
                    mma16816(acc[mi][nj], af[mi][0], af[mi][1], af[mi][2], af[mi][3],
                             bfr[nj][0], bfr[nj][1]);
        }
        __syncthreads();
    }

    // epilogue
#pragma unroll
    for (int mi = 0; mi < 4; mi++)
#pragma unroll
    for (int nj = 0; nj < 4; nj++) {
        int m = m0 + wm + mi*16 + gID;
        int n = n0 + wn + nj*8 + 2*tig;
        float* a = acc[mi][nj];
#pragma unroll
        for (int half = 0; half < 2; half++) {
            int mm = m + half * 8;
            float v0 = a[half*2 + 0], v1 = a[half*2 + 1];
            if (MODE == 1 || MODE == 2) {
                v0 = fmaxf(fmaf(v0, sc[n] * BNF, bi[n]), 0.f);
                v1 = fmaxf(fmaf(v1, sc[n+1] * BNF, bi[n+1]), 0.f);
            } else if (MODE == 3) {
                v0 += bi[n]; v1 += bi[n+1];
            } else if (MODE == 4) {
                const float2 e = *(const float2*)&extra[(long long)mm * N + n];
                v0 = fmaf(v0, 0.25f, e.x);
                v1 = fmaf(v1, 0.25f, e.y);
            }
            long long o = (long long)mm * N + n;
            *(float2*)&outf[o] = make_float2(v0, v1);
            if (MODE == 1) {
                bf16 h0, l0b, h1, l1b;
                split_bf(v0, h0, l0b);
                split_bf(v1, h1, l1b);
                __nv_bfloat162 hh; hh.x = h0; hh.y = h1;
                __nv_bfloat162 ll; ll.x = l0b; ll.y = l1b;
                *(__nv_bfloat162*)&ohi[o] = hh;
                *(__nv_bfloat162*)&olo[o] = ll;
            }
        }
    }
}

// ---------------- xproj (SIMT, unchanged): proj = xm @ Wperm.T ----------------
__global__ void __launch_bounds__(192) gemm_xproj()
{
    __shared__ float As[16][132];
    __shared__ float Bs[16][52];
    int tid = threadIdx.x;
    int zb = blockIdx.y;
    int m0 = blockIdx.x * 128;
    const float* Ab = g_xm + (long long)zb * LL * DI;
    const float* aptr = Ab + (long long)(m0 + tid) * DI;
    int bn = tid >> 2, bk = (tid & 3) * 4;
    const float* bptr = g_xpw + bn * DI + bk;
    int ty = tid / 12, txx = tid % 12;

    float4 pa[4], pbv;
    if (tid < 128) {
#pragma unroll
        for (int j = 0; j < 4; j++) pa[j] = ((const float4*)aptr)[j];
    }
    pbv = *(const float4*)bptr;

    float acc[8][4] = {};
    for (int k0 = 0; k0 < DI; k0 += 16) {
        if (tid < 128) {
#pragma unroll
            for (int j = 0; j < 4; j++) {
                As[j*4+0][tid] = pa[j].x;
                As[j*4+1][tid] = pa[j].y;
                As[j*4+2][tid] = pa[j].z;
                As[j*4+3][tid] = pa[j].w;
            }
        }
        Bs[bk+0][bn] = pbv.x; Bs[bk+1][bn] = pbv.y;
        Bs[bk+2][bn] = pbv.z; Bs[bk+3][bn] = pbv.w;
        __syncthreads();
        if (k0 + 16 < DI) {
            if (tid < 128) {
                const float* an = aptr + k0 + 16;
#pragma unroll
                for (int j = 0; j < 4; j++) pa[j] = ((const float4*)an)[j];
            }
            pbv = *(const float4*)(bptr + k0 + 16);
        }
#pragma unroll
        for (int k = 0; k < 16; k++) {
            float4 a0 = *(const float4*)&As[k][ty*8];
            float4 a1 = *(const float4*)&As[k][ty*8+4];
            float4 b4 = *(const float4*)&Bs[k][txx*4];
            float a[8] = {a0.x,a0.y,a0.z,a0.w,a1.x,a1.y,a1.z,a1.w};
            float bv[4] = {b4.x,b4.y,b4.z,b4.w};
#pragma unroll
            for (int i = 0; i < 8; i++)
#pragma unroll
                for (int j = 0; j < 4; j++)
                    acc[i][j] = fmaf(a[i], bv[j], acc[i][j]);
        }
        __syncthreads();
    }
#pragma unroll
    for (int i = 0; i < 8; i++) {
        int m = m0 + ty*8 + i;
        *(float4*)(g_projm + ((long long)zb * LL + m) * 48 + txx*4) =
            make_float4(acc[i][0], acc[i][1], acc[i][2], acc[i][3]);
    }
}

// ------- layernorm over c (rows contiguous), emits xn hi/lo -------------------
__global__ void __launch_bounds__(256) ln_k(const float* __restrict__ lng,
                                            const float* __restrict__ lnb)
{
    int w = threadIdx.x >> 5, lane = threadIdx.x & 31;
    int tok = blockIdx.x * 8 + w;
    const float* xp = g_xred + (long long)tok * CC;
    float4 v0 = *(const float4*)(xp + lane*4);
    float4 v1 = *(const float4*)(xp + 128 + lane*4);
    float s = v0.x+v0.y+v0.z+v0.w + v1.x+v1.y+v1.z+v1.w;
    float ss = v0.x*v0.x+v0.y*v0.y+v0.z*v0.z+v0.w*v0.w
             + v1.x*v1.x+v1.y*v1.y+v1.z*v1.z+v1.w*v1.w;
#pragma unroll
    for (int o = 16; o; o >>= 1) {
        s  += __shfl_xor_sync(0xffffffffu, s, o);
        ss += __shfl_xor_sync(0xffffffffu, ss, o);
    }
    float mu = s * (1.f/CC);
    float rstd = rsqrtf(ss * (1.f/CC) - mu*mu + 1e-5f);
    float4 g0 = *(const float4*)(lng + lane*4);
    float4 g1 = *(const float4*)(lng + 128 + lane*4);
    float4 b0 = *(const float4*)(lnb + lane*4);
    float4 b1 = *(const float4*)(lnb + 128 + lane*4);
    float vals[8] = {v0.x,v0.y,v0.z,v0.w, v1.x,v1.y,v1.z,v1.w};
    float gs[8] = {g0.x,g0.y,g0.z,g0.w, g1.x,g1.y,g1.z,g1.w};
    float bs[8] = {b0.x,b0.y,b0.z,b0.w, b1.x,b1.y,b1.z,b1.w};
    bf16 hi[8], lo[8];
#pragma unroll
    for (int i = 0; i < 8; i++) {
        float xn = (vals[i] - mu) * rstd * gs[i] + bs[i];
        split_bf(xn, hi[i], lo[i]);
    }
    long long base = (long long)tok * CC;
    *(uint2*)&g_xnhi[base + lane*4] = *(uint2*)&hi[0];
    *(uint2*)&g_xnhi[base + 128 + lane*4] = *(uint2*)&hi[4];
    *(uint2*)&g_xnlo[base + lane*4] = *(uint2*)&lo[0];
    *(uint2*)&g_xnlo[base + 128 + lane*4] = *(uint2*)&lo[4];
}

// -------- causal depthwise conv1d + silu (scan order), unchanged logic --------
#define CCT 64
__global__ void __launch_bounds__(512) conv1d_k(const float* __restrict__ cw,
                                                const float* __restrict__ cb)
{
    __shared__ int sl[CCT + 3];
    int d = threadIdx.x;
    int t0 = blockIdx.x * CCT;
    int b = blockIdx.y;
    int dir = blockIdx.z;
    if (d < CCT + 3) {
        int tt = t0 - 3 + d;
        sl[d] = (tt >= 0) ? g_map[dir * LL + tt] : 0;
    }
    __syncthreads();
    float w0 = cw[d*4+0], w1 = cw[d*4+1], w2 = cw[d*4+2], w3 = cw[d*4+3];
    float bias = cb[d];
    const float* xzb = g_xz + (long long)b * LL * 1024 + d;
    float x0 = 0.f, x1 = 0.f, x2 = 0.f;
    if (t0 > 0) {
        x0 = xzb[(long long)sl[0] * 1024];
        x1 = xzb[(long long)sl[1] * 1024];
        x2 = xzb[(long long)sl[2] * 1024];
    }
    float xn = xzb[(long long)sl[3] * 1024];
    float* yo = &g_xm[(((long long)dir * BB + b) * LL + t0) * DI + d];
    for (int i = 0; i < CCT; i++) {
        float xnn = (i + 1 < CCT) ? xzb[(long long)sl[i + 4] * 1024] : 0.f;
        float s = bias + w0*x0 + w1*x1 + w2*x2 + w3*xn;
        yo[(long long)i * DI] = silu_f(s);
        x0 = x1; x1 = x2; x2 = xn; xn = xnn;
    }
}

// ---------- dt = softplus(proj[:,:16] @ dt_w.T + dt_b) ------------------------
#define DTT 16
__global__ void __launch_bounds__(512) dt_k(const float* __restrict__ dtbias)
{
    __shared__ float pr[DTT][16];
    int d = threadIdx.x;
    int t0 = blockIdx.x * DTT;
    int b = blockIdx.y, dir = blockIdx.z;
    long long row0 = ((long long)dir * BB + b) * LL + t0;
    if (d < DTT * 16) {
        int ti = d >> 4, r = d & 15;
        pr[ti][r] = g_projm[(row0 + ti) * 48 + r];
    }
    float wreg[16];
#pragma unroll
    for (int r = 0; r < 16; r++) wreg[r] = g_dtwT[r * DI + d];
    float bias = dtbias[d];
    __syncthreads();
    float* out = &g_dtb[row0 * DI + d];
#pragma unroll 4
    for (int t = 0; t < DTT; t++) {
        float acc = bias;
#pragma unroll
        for (int r = 0; r < 16; r++) acc = fmaf(pr[t][r], wreg[r], acc);
        float dt = (acc > 15.f) ? acc : log1pf(expf(acc));
        out[(long long)t * DI] = dt;
    }
}

// ------------------------- selective scan (PF=8, float2 BC) -------------------
__global__ void __launch_bounds__(128) scan_k(const float* __restrict__ A_log,
                                              const float* __restrict__ Dp)
{
    int tid = threadIdx.x;
    int lane = tid & 31;
    int gwarp = blockIdx.x * 4 + (tid >> 5);
    int dir = gwarp >> 9;
    int b = (gwarp >> 8) & 1;
    int d = ((gwarp & 255) << 1) | (lane >> 4);
    int s = lane & 15;

    float Av = -expf(A_log[d * 16 + s]);
    float Dv = Dp[d];
    long long dbase = ((long long)dir * BB + b) * LL;
    const float* pdt = g_dtb + dbase * DI + d;
    const float* pxm = g_xm + dbase * DI + d;
    const float2* pbc = reinterpret_cast<const float2*>(g_projm) + dbase * 24 + 8 + s;
    bf16* py = g_y + dbase * DI + d;

    const int PF = 8;
    float f_dt[PF], f_x[PF];
    float2 f_bc[PF];
#pragma unroll
    for (int i = 0; i < PF; i++) {
        f_dt[i] = pdt[i * DI];
        f_x[i]  = pxm[i * DI];
        f_bc[i] = pbc[i * 24];
    }
    const float* qdt = pdt + PF * DI;
    const float* qxm = pxm + PF * DI;
    const float2* qbc = pbc + PF * 24;

    float h = 0.f;
    for (int t0 = 0; t0 < LL; t0 += PF) {
        bool pf = (t0 + PF < LL);
#pragma unroll
        for (int i = 0; i < PF; i++) {
            float dtv = f_dt[i], xv = f_x[i];
            float Bv = f_bc[i].x, Cv = f_bc[i].y;
            if (pf) {
                f_dt[i] = qdt[i * DI];
                f_x[i]  = qxm[i * DI];
                f_bc[i] = qbc[i * 24];
            }
            float dA = __expf(dtv * Av);
            h = fmaf(dA, h, dtv * xv * Bv);
            float part = h * Cv;
            part += __shfl_xor_sync(0xffffffffu, part, 1);
            part += __shfl_xor_sync(0xffffffffu, part, 2);
            part += __shfl_xor_sync(0xffffffffu, part, 4);
            part += __shfl_xor_sync(0xffffffffu, part, 8);
            if (s == 0) py[i * DI] = __float2bfloat16(fmaf(Dv, xv, part));
        }
        qdt += PF * DI; qxm += PF * DI; qbc += PF * 24; py += PF * DI;
    }
}

// ----- gather 4 dirs to natural order, silu(z) gate, emit ysum hi/lo ----------
__global__ void ysum_k()
{
    long long i = (long long)blockIdx.x * blockDim.x + threadIdx.x;
    if (i >= (long long)BL * DI) return;
    int d = (int)(i & (DI - 1));
    int l = (int)((i / DI) % LL);
    int b = (int)(i / ((long long)LL * DI));
    int t2 = (l % WW) * HH + l / WW;
    const long long st = (long long)BB * LL * DI;
    long long bb = (long long)b * LL * DI;
    float y = __bfloat162float(g_y[bb + (long long)l * DI + d])
            + __bfloat162float(g_y[st + bb + (long long)(LL - 1 - l) * DI + d])
            + __bfloat162float(g_y[2 * st + bb + (long long)t2 * DI + d])
            + __bfloat162float(g_y[3 * st + bb + (long long)(LL - 1 - t2) * DI + d]);
    float z = g_xz[((long long)b * LL + l) * 1024 + DI + d];
    float v = y * silu_f(z);
    bf16 h, lo;
    split_bf(v, h, lo);
    long long o = ((long long)b * LL + l) * DI + d;
    g_yshi[o] = h; g_yslo[o] = lo;
}

// ------------- depthwise 1x7 + 7x1 fused, token-major, emits hv hi/lo ---------
__global__ void __launch_bounds__(256) dwconv_k(
    const float* __restrict__ wh, const float* __restrict__ wv,
    const float* __restrict__ hg, const float* __restrict__ hb,
    const float* __restrict__ vg, const float* __restrict__ vb)
{
    int l = blockIdx.x;
    int b = blockIdx.y;
    int c = threadIdx.x;
    int y = l / WW, x = l % WW;
    const float* base = g_p + ((long long)b * HWW) * CC + c;
    float sh = 0.f, sv = 0.f;
#pragma unroll
    for (int j = 0; j < 7; j++) {
        int xx = x - 3 + j;
        if (xx >= 0 && xx < WW) sh += base[(long long)(y * WW + xx) * CC] * wh[c*7 + j];
        int yy = y - 3 + j;
        if (yy >= 0 && yy < HH) sv += base[(long long)(yy * WW + x) * CC] * wv[c*7 + j];
    }
    float rh = fmaxf(sh * (hg[c] * BNF) + hb[c], 0.f);
    float rv = fmaxf(sv * (vg[c] * BNF) + vb[c], 0.f);
    bf16 h, lo;
    split_bf(rh + rv, h, lo);
    long long o = ((long long)b * HWW + l) * CC + c;
    g_hvhi[o] = h; g_hvlo[o] = lo;
}

// ------------------------- SE head (token-major) ------------------------------
__global__ void mean1_k()
{
    int blk = blockIdx.x, b = blockIdx.y, c = threadIdx.x;
    float s = 0.f;
    for (int i = 0; i < 64; i++) {
        long long idx = ((long long)b * HWW + blk * 64 + i) * CC + c;
        s += g_featloc[idx] + g_featglob[idx];
    }
    g_msum[(b * 36 + blk) * CC + c] = s;
}
__global__ void mean2_k()
{
    int b = blockIdx.x, c = threadIdx.x;
    float s = 0.f;
    for (int i = 0; i < 36; i++) s += g_msum[(b * 36 + i) * CC + c];
    g_sv[b * CC + c] = s / (float)HWW;
}

__global__ void fc_k(const float* __restrict__ fc1, const float* __restrict__ fc2)
{
    int b = blockIdx.x;
    __shared__ float ss[CC], tt[16];
    int tid = threadIdx.x;
    ss[tid] = g_sv[b * CC + tid];
    __syncthreads();
    if (tid < 16) {
        float a = 0.f;
        for (int c = 0; c < CC; c++) a += ss[c] * fc1[tid * CC + c];
        tt[tid] = fmaxf(a, 0.f);
    }
    __syncthreads();
    float z0 = 0.f, z1 = 0.f;
#pragma unroll
    for (int m = 0; m < 16; m++) {
        z0 += tt[m] * fc2[tid * 16 + m];
        z1 += tt[m] * fc2[(CC + tid) * 16 + m];
    }
    float mx = fmaxf(z0, z1);
    float e0 = expf(z0 - mx), e1 = expf(z1 - mx);
    float w0 = e0 / (e0 + e1);
    g_wv[b * 2 * CC + tid] = w0;
    g_wv[b * 2 * CC + CC + tid] = 1.f - w0;
}

// ---- final combine + transpose [l][c] -> out[b][c][hw] -----------------------
__global__ void final_trans_k(float* __restrict__ out)
{
    __shared__ float tile[32][33];
    int b = blockIdx.z;
    int l0 = blockIdx.x * 32, c0 = blockIdx.y * 32;
    int tx = threadIdx.x, ty = threadIdx.y;   // (32,8)
    float w0 = g_wv[b * 2 * CC + c0 + tx];
    float w1 = g_wv[b * 2 * CC + CC + c0 + tx];
#pragma unroll
    for (int i = 0; i < 4; i++) {
        long long idx = ((long long)b * HWW + l0 + ty + i*8) * CC + c0 + tx;
        tile[ty + i*8][tx] = w0 * g_featloc[idx] + w1 * g_featglob[idx];
    }
    __syncthreads();
#pragma unroll
    for (int i = 0; i < 4; i++)
        out[((long long)b * CC + c0 + ty + i*8) * HWW + l0 + tx] = tile[tx][ty + i*8];
}

// ------------------------- launch ---------------------------------------------
extern "C" void kernel_launch(void* const* d_in, const int* in_sizes, int n_in,
                              void* d_out, int out_size)
{
    const float* x        = (const float*)d_in[0];
    const float* reduce_w = (const float*)d_in[1];
    const float* bn0_g    = (const float*)d_in[2];
    const float* bn0_b    = (const float*)d_in[3];
    const float* proj_w   = (const float*)d_in[4];
    const float* bn1_g    = (const float*)d_in[5];
    const float* bn1_b    = (const float*)d_in[6];
    const float* dwh_w    = (const float*)d_in[7];
    const float* bnh_g    = (const float*)d_in[8];
    const float* bnh_b    = (const float*)d_in[9];
    const float* dwv_w    = (const float*)d_in[10];
    const float* bnv_g    = (const float*)d_in[11];
    const float* bnv_b    = (const float*)d_in[12];
    const float* fus_w    = (const float*)d_in[13];
    const float* fus_b    = (const float*)d_in[14];
    const float* ln_g     = (const float*)d_in[15];
    const float* ln_b     = (const float*)d_in[16];
    const float* in_w     = (const float*)d_in[17];
    const float* conv_w   = (const float*)d_in[18];
    const float* conv_b   = (const float*)d_in[19];
    const float* xproj_w  = (const float*)d_in[20];
    const float* dt_w     = (const float*)d_in[21];
    const float* dt_b     = (const float*)d_in[22];
    const float* A_log    = (const float*)d_in[23];
    const float* Dp       = (const float*)d_in[24];
    const float* out_w    = (const float*)d_in[25];
    const float* fc1_w    = (const float*)d_in[26];
    const float* fc2_w    = (const float*)d_in[27];

    bf16 *xthi, *xtlo, *rwhi, *rwlo, *pwhi, *pwlo, *fwhi, *fwlo, *iwhi, *iwlo,
         *owhi, *owlo, *xrhi, *xrlo, *xnhi, *xnlo, *hvhi, *hvlo, *yshi, *yslo;
    float *xred, *p, *featloc, *featglob, *xz;
    cudaGetSymbolAddress((void**)&xthi, g_xthi);  cudaGetSymbolAddress((void**)&xtlo, g_xtlo);
    cudaGetSymbolAddress((void**)&rwhi, g_rwhi);  cudaGetSymbolAddress((void**)&rwlo, g_rwlo);
    cudaGetSymbolAddress((void**)&pwhi, g_pwhi);  cudaGetSymbolAddress((void**)&pwlo, g_pwlo);
    cudaGetSymbolAddress((void**)&fwhi, g_fwhi);  cudaGetSymbolAddress((void**)&fwlo, g_fwlo);
    cudaGetSymbolAddress((void**)&iwhi, g_iwhi);  cudaGetSymbolAddress((void**)&iwlo, g_iwlo);
    cudaGetSymbolAddress((void**)&owhi, g_owhi);  cudaGetSymbolAddress((void**)&owlo, g_owlo);
    cudaGetSymbolAddress((void**)&xrhi, g_xrhi);  cudaGetSymbolAddress((void**)&xrlo, g_xrlo);
    cudaGetSymbolAddress((void**)&xnhi, g_xnhi);  cudaGetSymbolAddress((void**)&xnlo, g_xnlo);
    cudaGetSymbolAddress((void**)&hvhi, g_hvhi);  cudaGetSymbolAddress((void**)&hvlo, g_hvlo);
    cudaGetSymbolAddress((void**)&yshi, g_yshi);  cudaGetSymbolAddress((void**)&yslo, g_yslo);
    cudaGetSymbolAddress((void**)&xred, g_xred);
    cudaGetSymbolAddress((void**)&p, g_p);
    cudaGetSymbolAddress((void**)&featloc, g_featloc);
    cudaGetSymbolAddress((void**)&featglob, g_featglob);
    cudaGetSymbolAddress((void**)&xz, g_xz);

    // 0) one-time prep (weight splits, maps)
    init_misc_k<<<2560, 256>>>(dt_w, xproj_w, reduce_w, proj_w, fus_w, in_w, out_w);
    // 1) input transpose + split
    trans_in_k<<<dim3(HWW/32, CIN/32, BB), dim3(32, 8)>>>(x);
    // 2) reduce: xred = relu(bn0(xT @ reduce_w.T))  [tensor], emits fp32 + hi/lo
    gemm_t3<1><<<dim3(4, 36), 128>>>(xthi, xtlo, rwhi, rwlo,
        xred, xrhi, xrlo, BL, CC, CIN, bn0_g, bn0_b, (const float*)0);
    // 3) layernorm -> xn hi/lo
    ln_k<<<BL/8, 256>>>(ln_g, ln_b);
    // 4) in_proj: xz = xn @ in_w.T  [tensor]
    gemm_t3<0><<<dim3(16, 36), 128>>>(xnhi, xnlo, iwhi, iwlo,
        xz, (bf16*)0, (bf16*)0, BL, 2*DI, CC, (const float*)0, (const float*)0, (const float*)0);
    // 5) causal conv1d + silu -> scan-ordered xm
    conv1d_k<<<dim3(LL/CCT, BB, 4), 512>>>(conv_w, conv_b);
    // 6) xproj (SIMT) -> projm
    gemm_xproj<<<dim3(18, 8), 192>>>();
    // 7) dt
    dt_k<<<dim3(LL/DTT, BB, 4), 512>>>(dt_b);
    // 8) selective scan
    scan_k<<<512, 128>>>(A_log, Dp);
    // 9) gather + gate -> ysum hi/lo
    ysum_k<<<(BL*DI + 255)/256, 256>>>();
    // 10) feat_global = 0.25*(ysum @ out_w.T) + xred  [tensor]
    gemm_t3<4><<<dim3(4, 36), 128>>>(yshi, yslo, owhi, owlo,
        featglob, (bf16*)0, (bf16*)0, BL, CC, DI, (const float*)0, (const float*)0, xred);
    // 11) p = relu(bn1(xred @ proj_w.T))  [tensor]
    gemm_t3<2><<<dim3(4, 36), 128>>>(xrhi, xrlo, pwhi, pwlo,
        p, (bf16*)0, (bf16*)0, BL, CC, CC, bn1_g, bn1_b, (const float*)0);
    // 12) depthwise h+v -> hv hi/lo
    dwconv_k<<<dim3(HWW, BB), 256>>>(dwh_w, dwv_w, bnh_g, bnh_b, bnv_g, bnv_b);
    // 13) feat_local = hv @ fus_w.T + fus_b  [tensor]
    gemm_t3<3><<<dim3(4, 36), 128>>>(hvhi, hvlo, fwhi, fwlo,
        featloc, (bf16*)0, (bf16*)0, BL, CC, CC, (const float*)0, fus_b, (const float*)0);
    // 14-16) SE head + final combine/transpose
    mean1_k<<<dim3(36, BB), 256>>>();
    mean2_k<<<BB, 256>>>();
    fc_k<<<BB, 256>>>(fc1_w, fc2_w);
    final_trans_k<<<dim3(HWW/32, CC/32, BB), dim3(32, 8)>>>((float*)d_out);
}

// round 11
// speedup vs baseline: 1.5323x; 1.5323x over previous
#include <cuda_runtime.h>
#include <cuda_bf16.h>
#include <stdint.h>
#include <math.h>

#define BB  2
#define CIN 512
#define CC  256
#define HH  48
#define WW  48
#define HWW 2304
#define LL  2304
#define DI  512
#define BL  (BB*LL)
#define BNF 0.9999950000374997f   /* 1/sqrt(1+1e-5) */

typedef __nv_bfloat16 bf16;

// ------------------------- static scratch (no allocs) -------------------------
__device__ __align__(256) float g_xred[BB*CC*HWW];
__device__ __align__(256) float g_p[BB*CC*HWW];
__device__ __align__(256) float g_hv[BB*CC*HWW];
__device__ __align__(256) float g_featloc[BB*CC*HWW];
__device__ __align__(256) float g_featglob[BB*CC*HWW];
__device__ __align__(256) float g_mu[BB*HWW];
__device__ __align__(256) float g_rstd[BB*HWW];
__device__ __align__(256) float g_xn[BL*CC];          // (b,l,c)
__device__ __align__(256) bf16  g_xnhi[BL*CC];        // split of xn
__device__ __align__(256) bf16  g_xnlo[BL*CC];
__device__ __align__(256) bf16  g_iwhi[2*DI*CC];      // split of in_w
__device__ __align__(256) bf16  g_iwlo[2*DI*CC];
__device__ __align__(256) float g_xz[BL*2*DI];        // (b,l,1024): xm0 | z
__device__ __align__(256) float g_xm[4*BL*DI];        // (dir,b,t,d) SCAN order
__device__ __align__(256) float g_projm[4*BL*48];     // (dir,b,t,48): [dt16][B,C interleaved]
__device__ __align__(256) float g_dtb[4*BL*DI];       // SCAN order
__device__ __align__(256) bf16  g_y[4*BL*DI];         // SCAN order, ungated, bf16
__device__ __align__(256) float g_ysum[BL*DI];        // natural order, gated
__device__ __align__(256) float g_dtwT[16*DI];        // transposed dt_w
__device__ __align__(256) float g_xpw[48*DI];         // row-permuted xproj_w
__device__ __align__(256) int   g_map[4*LL];          // dir,t -> l
__device__ __align__(256) float g_sv[BB*CC];
__device__ __align__(256) float g_wv[BB*2*CC];

__device__ __forceinline__ int seq_map(int dir, int t) {
    if (dir == 0) return t;
    if (dir == 1) return LL - 1 - t;
    int u = (dir == 2) ? t : (LL - 1 - t);
    int h = u % HH, w = u / HH;
    return h * WW + w;
}

__device__ __forceinline__ float silu_f(float x) { return x / (1.f + __expf(-x)); }
__device__ __forceinline__ void split_bf(float v, bf16& h, bf16& l) {
    h = __float2bfloat16(v);
    l = __float2bfloat16(v - __bfloat162float(h));
}

// ------------------ one-time weight/layout prep --------------------------------
__global__ void init_misc_k(const float* __restrict__ dtw, const float* __restrict__ xpw,
                            const float* __restrict__ iw)
{
    int i = blockIdx.x * 256 + threadIdx.x;
    if (i < 16 * DI) {                       // dt_w transpose
        int dd = i >> 4, r = i & 15;
        g_dtwT[r * DI + dd] = dtw[i];
    }
    if (i < 4 * LL) {                        // scan-order maps
        int dir = i / LL, t = i % LL;
        g_map[i] = seq_map(dir, t);
    }
    if (i < 48 * DI) {                       // xproj weight row-permutation
        int j = i >> 9, k = i & 511;
        int src = (j < 16) ? j
                : (((j - 16) & 1) ? 32 + ((j - 16) >> 1) : 16 + ((j - 16) >> 1));
        g_xpw[i] = xpw[src * DI + k];
    }
    if (i < 2 * DI * CC)                     // in_w split
        split_bf(iw[i], g_iwhi[i], g_iwlo[i]);
}

// ======================= tensor-core in_proj (A/B test) =======================
// xz[m][n] = sum_k xn[m][k] * in_w[n][k], split 3-pass bf16.
// Block 128x128, 256 threads (8 warps, warp tile 64x32). grid (8, 36).
#define ASTR 40
__device__ __forceinline__ void mma16816(float* d, uint32_t a0, uint32_t a1,
                                         uint32_t a2, uint32_t a3,
                                         uint32_t b0, uint32_t b1)
{
    asm volatile(
        "mma.sync.aligned.m16n8k16.row.col.f32.bf16.bf16.f32 "
        "{%0,%1,%2,%3}, {%4,%5,%6,%7}, {%8,%9}, {%0,%1,%2,%3};\n"
        : "+f"(d[0]), "+f"(d[1]), "+f"(d[2]), "+f"(d[3])
        : "r"(a0), "r"(a1), "r"(a2), "r"(a3), "r"(b0), "r"(b1));
}

__global__ void __launch_bounds__(256) gemm_inproj_t3()
{
    __shared__ bf16 As[128 * ASTR];
    __shared__ bf16 Bs[128 * ASTR];
    const int K = CC;                 // 256
    const int N = 2 * DI;             // 1024
    int tid = threadIdx.x;
    int warp = tid >> 5, lane = tid & 31;
    int gID = lane >> 2, tig = lane & 3;
    int wm = (warp >> 2) * 64, wn = (warp & 3) * 32;
    int m0 = blockIdx.y * 128, n0 = blockIdx.x * 128;

    int u0 = tid, u1 = tid + 256;
    int ar0 = u0 >> 2, ac0 = (u0 & 3) * 8;
    int ar1 = u1 >> 2, ac1 = (u1 & 3) * 8;

    uint4 ra[2], rb[2];
    ra[0] = *(const uint4*)(g_xnhi + (long long)(m0 + ar0) * K + ac0);
    ra[1] = *(const uint4*)(g_xnhi + (long long)(m0 + ar1) * K + ac1);
    rb[0] = *(const uint4*)(g_iwhi + (long long)(n0 + ar0) * K + ac0);
    rb[1] = *(const uint4*)(g_iwhi + (long long)(n0 + ar1) * K + ac1);

    float acc[4][4][4] = {};
    const int G = 24;                 // 3 passes * (256/32)

    for (int g = 0; g < G; g++) {
        *(uint4*)&As[ar0 * ASTR + ac0] = ra[0];
        *(uint4*)&As[ar1 * ASTR + ac1] = ra[1];
        *(uint4*)&Bs[ar0 * ASTR + ac0] = rb[0];
        *(uint4*)&Bs[ar1 * ASTR + ac1] = rb[1];
        __syncthreads();
        int gn = g + 1;
        if (gn < G) {
            int pass = gn >> 3;
            int kk = (gn & 7) * 32;
            const bf16* Ag = (pass == 1) ? g_xnlo : g_xnhi;
            const bf16* Bg = (pass == 2) ? g_iwlo : g_iwhi;
            ra[0] = *(const uint4*)(Ag + (long long)(m0 + ar0) * K + kk + ac0);
            ra[1] = *(const uint4*)(Ag + (long long)(m0 + ar1) * K + kk + ac1);
            rb[0] = *(const uint4*)(Bg + (long long)(n0 + ar0) * K + kk + ac0);
            rb[1] = *(const uint4*)(Bg + (long long)(n0 + ar1) * K + kk + ac1);
        }
#pragma unroll
        for (int ks = 0; ks < 32; ks += 16) {
            uint32_t af[4][4], bfr[4][2];
#pragma unroll
            for (int mi = 0; mi < 4; mi++) {
                int r = wm + mi*16 + gID;
                af[mi][0] = *(const uint32_t*)&As[r * ASTR + ks + 2*tig];
                af[mi][1] = *(const uint32_t*)&As[(r+8) * ASTR + ks + 2*tig];
                af[mi][2] = *(const uint32_t*)&As[r * ASTR + ks + 2*tig + 8];
                af[mi][3] = *(const uint32_t*)&As[(r+8) * ASTR + ks + 2*tig + 8];
            }
#pragma unroll
            for (int nj = 0; nj < 4; nj++) {
                int r = wn + nj*8 + gID;
                bfr[nj][0] = *(const uint32_t*)&Bs[r * ASTR + ks + 2*tig];
                bfr[nj][1] = *(const uint32_t*)&Bs[r * ASTR + ks + 2*tig + 8];
            }
#pragma unroll
            for (int mi = 0; mi < 4; mi++)
#pragma unroll
                for (int nj = 0; nj < 4; nj++)
                    mma16816(acc[mi][nj], af[mi][0], af[mi][1], af[mi][2], af[mi][3],
                             bfr[nj][0], bfr[nj][1]);
        }
        __syncthreads();
    }

#pragma unroll
    for (int mi = 0; mi < 4; mi++)
#pragma unroll
    for (int nj = 0; nj < 4; nj++) {
        int m = m0 + wm + mi*16 + gID;
        int n = n0 + wn + nj*8 + 2*tig;
        float* a = acc[mi][nj];
#pragma unroll
        for (int half = 0; half < 2; half++) {
            int mm = m + half * 8;
            *(float2*)&g_xz[(long long)mm * N + n] = make_float2(a[half*2], a[half*2+1]);
        }
    }
}

// ---------------- 128x64 SGEMM, k-tile 32 (R7 SIMT version) -------------------
template<int MODE, bool TB>
__global__ void __launch_bounds__(256) gemm128(
    const float* __restrict__ A, const float* __restrict__ B, float* __restrict__ C,
    int M, int N, int K,
    long long sA, long long sB, long long sC,
    const float* __restrict__ scale, const float* __restrict__ bias,
    const float* __restrict__ extra, long long sE)
{
    __shared__ float As[32][132];
    __shared__ float Bs[32][68];
    const float* Ab = A + (long long)blockIdx.z * sA;
    const float* Bb = B + (long long)blockIdx.z * sB;
    float* Cb = C + (long long)blockIdx.z * sC;
    int tid = threadIdx.x;
    int m0 = blockIdx.y * 128, n0 = blockIdx.x * 64;
    int tx = tid & 15, ty = tid >> 4;

    int arow = tid >> 3;
    int akk = (tid & 7) * 4;
    const float* aptr = Ab + (long long)(m0 + arow) * K + akk;
    const long long astep = (long long)32 * K;

    int bk, bn;
    const float* bptr;
    if (TB) {
        bn = tid >> 3;
        bk = (tid & 7) * 4;
        bptr = Bb + (long long)(n0 + bn) * K + bk;
    } else {
        bk = (tid >> 4) * 2;
        bn = (tid & 15) * 4;
        bptr = Bb + (long long)bk * N + n0 + bn;
    }

    float4 pa[4], pb[2];
#pragma unroll
    for (int i = 0; i < 4; i++) pa[i] = *(const float4*)(aptr + i * astep);
    if (TB) {
        pb[0] = *(const float4*)(bptr);
        pb[1] = *(const float4*)(bptr + astep);
    } else {
        pb[0] = *(const float4*)(bptr);
        pb[1] = *(const float4*)(bptr + N);
    }

    float acc[8][4] = {};

    for (int k0 = 0; k0 < K; k0 += 32) {
#pragma unroll
        for (int i = 0; i < 4; i++) {
            As[akk+0][arow+32*i] = pa[i].x;
            As[akk+1][arow+32*i] = pa[i].y;
            As[akk+2][arow+32*i] = pa[i].z;
            As[akk+3][arow+32*i] = pa[i].w;
        }
        if (TB) {
            Bs[bk+0][bn] = pb[0].x; Bs[bk+1][bn] = pb[0].y;
            Bs[bk+2][bn] = pb[0].z; Bs[bk+3][bn] = pb[0].w;
            Bs[bk+0][bn+32] = pb[1].x; Bs[bk+1][bn+32] = pb[1].y;
            Bs[bk+2][bn+32] = pb[1].z; Bs[bk+3][bn+32] = pb[1].w;
        } else {
            *(float4*)&Bs[bk][bn] = pb[0];
            *(float4*)&Bs[bk+1][bn] = pb[1];
        }
        __syncthreads();
        if (k0 + 32 < K) {
            aptr += 32;
#pragma unroll
            for (int i = 0; i < 4; i++) pa[i] = *(const float4*)(aptr + i * astep);
            if (TB) {
                bptr += 32;
                pb[0] = *(const float4*)(bptr);
                pb[1] = *(const float4*)(bptr + astep);
            } else {
                bptr += (long long)32 * N;
                pb[0] = *(const float4*)(bptr);
                pb[1] = *(const float4*)(bptr + N);
            }
        }
#pragma unroll 8
        for (int k = 0; k < 32; k++) {
            float4 a0 = *(const float4*)&As[k][ty*8];
            float4 a1 = *(const float4*)&As[k][ty*8+4];
            float4 b4 = *(const float4*)&Bs[k][tx*4];
            float a[8] = {a0.x,a0.y,a0.z,a0.w,a1.x,a1.y,a1.z,a1.w};
            float bbv[4] = {b4.x,b4.y,b4.z,b4.w};
#pragma unroll
            for (int i = 0; i < 8; i++)
#pragma unroll
                for (int j = 0; j < 4; j++)
                    acc[i][j] = fmaf(a[i], bbv[j], acc[i][j]);
        }
        __syncthreads();
    }

#pragma unroll
    for (int i = 0; i < 8; i++) {
        int m = m0 + ty*8 + i;
        float sc = 1.f, bi = 0.f;
        if (MODE == 1) { sc = scale[m] * BNF; bi = bias[m]; }
        if (MODE == 2) { bi = bias[m]; }
        int n = n0 + tx*4;
        float v[4];
#pragma unroll
        for (int j = 0; j < 4; j++) {
            float t = acc[i][j];
            if (MODE == 1) t = fmaxf(fmaf(t, sc, bi), 0.f);
            else if (MODE == 2) t = t + bi;
            else if (MODE == 3)
                t = t * 0.25f + extra[(long long)blockIdx.z * sE + (long long)m * N + n + j];
            v[j] = t;
        }
        *(float4*)(Cb + (long long)m * N + n) = make_float4(v[0], v[1], v[2], v[3]);
    }
}

// ---------------- xproj: (dir,b) x [2304 x 48] = xm @ Wperm.T -----------------
__global__ void __launch_bounds__(192) gemm_xproj()
{
    __shared__ float As[16][132];
    __shared__ float Bs[16][52];
    int tid = threadIdx.x;
    int zb = blockIdx.y;
    int m0 = blockIdx.x * 128;
    const float* Ab = g_xm + (long long)zb * LL * DI;
    const float* aptr = Ab + (long long)(m0 + tid) * DI;
    int bn = tid >> 2, bk = (tid & 3) * 4;
    const float* bptr = g_xpw + bn * DI + bk;
    int ty = tid / 12, txx = tid % 12;

    float4 pa[4], pbv;
    if (tid < 128) {
#pragma unroll
        for (int j = 0; j < 4; j++) pa[j] = ((const float4*)aptr)[j];
    }
    pbv = *(const float4*)bptr;

    float acc[8][4] = {};
    for (int k0 = 0; k0 < DI; k0 += 16) {
        if (tid < 128) {
#pragma unroll
            for (int j = 0; j < 4; j++) {
                As[j*4+0][tid] = pa[j].x;
                As[j*4+1][tid] = pa[j].y;
                As[j*4+2][tid] = pa[j].z;
                As[j*4+3][tid] = pa[j].w;
            }
        }
        Bs[bk+0][bn] = pbv.x; Bs[bk+1][bn] = pbv.y;
        Bs[bk+2][bn] = pbv.z; Bs[bk+3][bn] = pbv.w;
        __syncthreads();
        if (k0 + 16 < DI) {
            if (tid < 128) {
                const float* an = aptr + k0 + 16;
#pragma unroll
                for (int j = 0; j < 4; j++) pa[j] = ((const float4*)an)[j];
            }
            pbv = *(const float4*)(bptr + k0 + 16);
        }
#pragma unroll
        for (int k = 0; k < 16; k++) {
            float4 a0 = *(const float4*)&As[k][ty*8];
            float4 a1 = *(const float4*)&As[k][ty*8+4];
            float4 b4 = *(const float4*)&Bs[k][txx*4];
            float a[8] = {a0.x,a0.y,a0.z,a0.w,a1.x,a1.y,a1.z,a1.w};
            float bv[4] = {b4.x,b4.y,b4.z,b4.w};
#pragma unroll
            for (int i = 0; i < 8; i++)
#pragma unroll
                for (int j = 0; j < 4; j++)
                    acc[i][j] = fmaf(a[i], bv[j], acc[i][j]);
        }
        __syncthreads();
    }
#pragma unroll
    for (int i = 0; i < 8; i++) {
        int m = m0 + ty*8 + i;
        *(float4*)(g_projm + ((long long)zb * LL + m) * 48 + txx*4) =
            make_float4(acc[i][0], acc[i][1], acc[i][2], acc[i][3]);
    }
}

// ------------------------- depthwise 1x7 + 7x1 fused --------------------------
__global__ void dwconv_k(const float* __restrict__ p,
                         const float* __restrict__ wh, const float* __restrict__ wv,
                         const float* __restrict__ hg, const float* __restrict__ hb,
                         const float* __restrict__ vg, const float* __restrict__ vb,
                         float* __restrict__ out)
{
    int idx = blockIdx.x * blockDim.x + threadIdx.x;
    if (idx >= BB * CC * HWW) return;
    int l = idx % HWW;
    int c = (idx / HWW) % CC;
    int y = l / WW, x = l % WW;
    const float* base = p + (idx - l);
    float sh = 0.f, sv = 0.f;
#pragma unroll
    for (int j = 0; j < 7; j++) {
        int xx = x - 3 + j;
        if (xx >= 0 && xx < WW) sh += base[y * WW + xx] * wh[c * 7 + j];
        int yy = y - 3 + j;
        if (yy >= 0 && yy < HH) sv += base[yy * WW + x] * wv[c * 7 + j];
    }
    float rh = fmaxf(sh * (hg[c] * BNF) + hb[c], 0.f);
    float rv = fmaxf(sv * (vg[c] * BNF) + vb[c], 0.f);
    out[idx] = rh + rv;
}

// ------------------------- layernorm over C -----------------------------------
__global__ void ln_stats_k(const float* __restrict__ x)
{
    int l = blockIdx.x * blockDim.x + threadIdx.x;
    int b = blockIdx.y;
    if (l >= HWW) return;
    const float* xp = x + (long long)b * CC * HWW + l;
    float s = 0.f, ss = 0.f;
#pragma unroll 8
    for (int c = 0; c < CC; c++) { float v = xp[(long long)c * HWW]; s += v; ss += v * v; }
    float mu = s * (1.f / CC);
    float var = ss * (1.f / CC) - mu * mu;
    g_mu[b * HWW + l] = mu;
    g_rstd[b * HWW + l] = rsqrtf(var + 1e-5f);
}

__global__ void trans_norm_k(const float* __restrict__ x,
                             const float* __restrict__ lng, const float* __restrict__ lnb)
{
    __shared__ float tile[32][33];
    int b = blockIdx.z;
    int l0 = blockIdx.x * 32, c0 = blockIdx.y * 32;
    int tx = threadIdx.x, ty = threadIdx.y;   // (32,8)
#pragma unroll
    for (int i = 0; i < 4; i++) {
        int c = c0 + ty + i * 8;
        tile[ty + i * 8][tx] = x[((long long)b * CC + c) * HWW + l0 + tx];
    }
    __syncthreads();
#pragma unroll
    for (int i = 0; i < 4; i++) {
        int l = l0 + ty + i * 8;
        int c = c0 + tx;
        float v = (tile[tx][ty + i * 8] - g_mu[b * HWW + l]) * g_rstd[b * HWW + l];
        float xn = v * lng[c] + lnb[c];
        long long o = ((long long)b * HWW + l) * CC + c;
        g_xn[o] = xn;
        bf16 h, lo;
        split_bf(xn, h, lo);
        g_xnhi[o] = h;
        g_xnlo[o] = lo;
    }
}

// -------- causal depthwise conv1d + silu, chunked, smem map -------------------
#define CCT 64
__global__ void __launch_bounds__(512) conv1d_k(const float* __restrict__ cw,
                                                const float* __restrict__ cb)
{
    __shared__ int sl[CCT + 3];
    int d = threadIdx.x;
    int t0 = blockIdx.x * CCT;
    int b = blockIdx.y;
    int dir = blockIdx.z;
    if (d < CCT + 3) {
        int tt = t0 - 3 + d;
        sl[d] = (tt >= 0) ? g_map[dir * LL + tt] : 0;
    }
    __syncthreads();
    float w0 = cw[d * 4 + 0], w1 = cw[d * 4 + 1], w2 = cw[d * 4 + 2], w3 = cw[d * 4 + 3];
    float bias = cb[d];
    const float* xzb = g_xz + (long long)b * LL * 1024 + d;
    float x0 = 0.f, x1 = 0.f, x2 = 0.f;
    if (t0 > 0) {
        x0 = xzb[(long long)sl[0] * 1024];
        x1 = xzb[(long long)sl[1] * 1024];
        x2 = xzb[(long long)sl[2] * 1024];
    }
    float xn = xzb[(long long)sl[3] * 1024];
    float* yo = &g_xm[(((long long)dir * BB + b) * LL + t0) * DI + d];
    for (int i = 0; i < CCT; i++) {
        float xnn = (i + 1 < CCT) ? xzb[(long long)sl[i + 4] * 1024] : 0.f;
        float s = bias + w0 * x0 + w1 * x1 + w2 * x2 + w3 * xn;
        yo[(long long)i * DI] = silu_f(s);
        x0 = x1; x1 = x2; x2 = xn; xn = xnn;
    }
}

// ---------- dt = softplus(proj[:,:16] @ dt_w.T + dt_b), 16 t per block --------
#define DTT 16
__global__ void __launch_bounds__(512) dt_k(const float* __restrict__ dtbias)
{
    __shared__ float pr[DTT][16];
    int d = threadIdx.x;
    int t0 = blockIdx.x * DTT;
    int b = blockIdx.y, dir = blockIdx.z;
    long long row0 = ((long long)dir * BB + b) * LL + t0;
    if (d < DTT * 16) {
        int ti = d >> 4, r = d & 15;
        pr[ti][r] = g_projm[(row0 + ti) * 48 + r];
    }
    float wreg[16];
#pragma unroll
    for (int r = 0; r < 16; r++) wreg[r] = g_dtwT[r * DI + d];
    float bias = dtbias[d];
    __syncthreads();
    float* out = &g_dtb[row0 * DI + d];
#pragma unroll 4
    for (int t = 0; t < DTT; t++) {
        float acc = bias;
#pragma unroll
        for (int r = 0; r < 16; r++) acc = fmaf(pr[t][r], wreg[r], acc);
        float dt = (acc > 15.f) ? acc : log1pf(expf(acc));
        out[(long long)t * DI] = dt;
    }
}

// ------------------------- selective scan (PF=8, float2 BC) -------------------
__global__ void __launch_bounds__(128) scan_k(const float* __restrict__ A_log,
                                              const float* __restrict__ Dp)
{
    int tid = threadIdx.x;
    int lane = tid & 31;
    int gwarp = blockIdx.x * 4 + (tid >> 5);
    int dir = gwarp >> 9;
    int b = (gwarp >> 8) & 1;
    int d = ((gwarp & 255) << 1) | (lane >> 4);
    int s = lane & 15;

    float Av = -expf(A_log[d * 16 + s]);
    float Dv = Dp[d];
    long long dbase = ((long long)dir * BB + b) * LL;
    const float* pdt = g_dtb + dbase * DI + d;
    const float* pxm = g_xm + dbase * DI + d;
    const float2* pbc = reinterpret_cast<const float2*>(g_projm) + dbase * 24 + 8 + s;
    bf16* py = g_y + dbase * DI + d;

    const int PF = 8;
    float f_dt[PF], f_x[PF];
    float2 f_bc[PF];
#pragma unroll
    for (int i = 0; i < PF; i++) {
        f_dt[i] = pdt[i * DI];
        f_x[i]  = pxm[i * DI];
        f_bc[i] = pbc[i * 24];
    }
    const float* qdt = pdt + PF * DI;
    const float* qxm = pxm + PF * DI;
    const float2* qbc = pbc + PF * 24;

    float h = 0.f;
    for (int t0 = 0; t0 < LL; t0 += PF) {
        bool pf = (t0 + PF < LL);
#pragma unroll
        for (int i = 0; i < PF; i++) {
            float dtv = f_dt[i], xv = f_x[i];
            float Bv = f_bc[i].x, Cv = f_bc[i].y;
            if (pf) {
                f_dt[i] = qdt[i * DI];
                f_x[i]  = qxm[i * DI];
                f_bc[i] = qbc[i * 24];
            }
            float dA = __expf(dtv * Av);
            h = fmaf(dA, h, dtv * xv * Bv);
            float part = h * Cv;
            part += __shfl_xor_sync(0xffffffffu, part, 1);
            part += __shfl_xor_sync(0xffffffffu, part, 2);
            part += __shfl_xor_sync(0xffffffffu, part, 4);
            part += __shfl_xor_sync(0xffffffffu, part, 8);
            if (s == 0) py[i * DI] = __float2bfloat16(fmaf(Dv, xv, part));
        }
        qdt += PF * DI; qxm += PF * DI; qbc += PF * 24; py += PF * DI;
    }
}

// ----- gather 4 directions back to natural order, apply silu(z) gate ----------
__global__ void ysum_k()
{
    long long i = (long long)blockIdx.x * blockDim.x + threadIdx.x;
    if (i >= (long long)BL * DI) return;
    int d = (int)(i & (DI - 1));
    int l = (int)((i / DI) % LL);
    int b = (int)(i / ((long long)LL * DI));
    int t2 = (l % WW) * HH + l / WW;
    const long long st = (long long)BB * LL * DI;
    long long bb = (long long)b * LL * DI;
    float y = __bfloat162float(g_y[bb + (long long)l * DI + d])
            + __bfloat162float(g_y[st + bb + (long long)(LL - 1 - l) * DI + d])
            + __bfloat162float(g_y[2 * st + bb + (long long)t2 * DI + d])
            + __bfloat162float(g_y[3 * st + bb + (long long)(LL - 1 - t2) * DI + d]);
    float z = g_xz[((long long)b * LL + l) * 1024 + DI + d];
    g_ysum[((long long)b * LL + l) * DI + d] = y * silu_f(z);
}

// ------------------------- SE head --------------------------------------------
__global__ void mean_k()
{
    int c = blockIdx.x, b = blockIdx.y;
    long long base = ((long long)b * CC + c) * HWW;
    float s = 0.f;
    for (int l = threadIdx.x; l < HWW; l += 256)
        s += g_featloc[base + l] + g_featglob[base + l];
    __shared__ float red[256];
    red[threadIdx.x] = s;
    __syncthreads();
    for (int o = 128; o; o >>= 1) {
        if (threadIdx.x < o) red[threadIdx.x] += red[threadIdx.x + o];
        __syncthreads();
    }
    if (threadIdx.x == 0) g_sv[b * CC + c] = red[0] / (float)HWW;
}

__global__ void fc_k(const float* __restrict__ fc1, const float* __restrict__ fc2)
{
    int b = blockIdx.x;
    __shared__ float ss[CC], tt[16];
    int tid = threadIdx.x;
    ss[tid] = g_sv[b * CC + tid];
    __syncthreads();
    if (tid < 16) {
        float a = 0.f;
        for (int c = 0; c < CC; c++) a += ss[c] * fc1[tid * CC + c];
        tt[tid] = fmaxf(a, 0.f);
    }
    __syncthreads();
    float z0 = 0.f, z1 = 0.f;
#pragma unroll
    for (int m = 0; m < 16; m++) {
        z0 += tt[m] * fc2[tid * 16 + m];
        z1 += tt[m] * fc2[(CC + tid) * 16 + m];
    }
    float mx = fmaxf(z0, z1);
    float e0 = expf(z0 - mx), e1 = expf(z1 - mx);
    float w0 = e0 / (e0 + e1);
    g_wv[b * 2 * CC + tid] = w0;
    g_wv[b * 2 * CC + CC + tid] = 1.f - w0;
}

__global__ void final_k(float* __restrict__ out)
{
    long long i = (long long)blockIdx.x * 256 + threadIdx.x;
    if (i >= (long long)BB * CC * HWW) return;
    int c = (int)((i / HWW) % CC);
    int b = (int)(i / ((long long)CC * HWW));
    out[i] = g_wv[b * 2 * CC + c] * g_featloc[i] + g_wv[b * 2 * CC + CC + c] * g_featglob[i];
}

// ------------------------- launch ---------------------------------------------
extern "C" void kernel_launch(void* const* d_in, const int* in_sizes, int n_in,
                              void* d_out, int out_size)
{
    const float* x        = (const float*)d_in[0];
    const float* reduce_w = (const float*)d_in[1];
    const float* bn0_g    = (const float*)d_in[2];
    const float* bn0_b    = (const float*)d_in[3];
    const float* proj_w   = (const float*)d_in[4];
    const float* bn1_g    = (const float*)d_in[5];
    const float* bn1_b    = (const float*)d_in[6];
    const float* dwh_w    = (const float*)d_in[7];
    const float* bnh_g    = (const float*)d_in[8];
    const float* bnh_b    = (const float*)d_in[9];
    const float* dwv_w    = (const float*)d_in[10];
    const float* bnv_g    = (const float*)d_in[11];
    const float* bnv_b    = (const float*)d_in[12];
    const float* fus_w    = (const float*)d_in[13];
    const float* fus_b    = (const float*)d_in[14];
    const float* ln_g     = (const float*)d_in[15];
    const float* ln_b     = (const float*)d_in[16];
    const float* in_w     = (const float*)d_in[17];
    const float* conv_w   = (const float*)d_in[18];
    const float* conv_b   = (const float*)d_in[19];
    const float* xproj_w  = (const float*)d_in[20];
    const float* dt_w     = (const float*)d_in[21];
    const float* dt_b     = (const float*)d_in[22];
    const float* A_log    = (const float*)d_in[23];
    const float* Dp       = (const float*)d_in[24];
    const float* out_w    = (const float*)d_in[25];
    const float* fc1_w    = (const float*)d_in[26];
    const float* fc2_w    = (const float*)d_in[27];

    float *xred, *p, *hv, *featloc, *featglob, *xz, *ysum;
    cudaGetSymbolAddress((void**)&xred, g_xred);
    cudaGetSymbolAddress((void**)&p, g_p);
    cudaGetSymbolAddress((void**)&hv, g_hv);
    cudaGetSymbolAddress((void**)&featloc, g_featloc);
    cudaGetSymbolAddress((void**)&featglob, g_featglob);
    cudaGetSymbolAddress((void**)&xz, g_xz);
    cudaGetSymbolAddress((void**)&ysum, g_ysum);

    // 0) one-time weight prep (+ in_w split)
    init_misc_k<<<1024, 256>>>(dt_w, xproj_w, in_w);
    // 1) x = relu(bn0(reduce_w @ xin))
    gemm128<1, false><<<dim3(36, 2, BB), 256>>>(reduce_w, x, xred, 256, 2304, 512,
        0, (long long)CIN * HWW, (long long)CC * HWW, bn0_g, bn0_b, (const float*)0, 0);
    // 2,3) layernorm over C (also emits xn hi/lo splits)
    ln_stats_k<<<dim3((HWW + 255) / 256, BB), 256>>>(xred);
    trans_norm_k<<<dim3(HWW / 32, CC / 32, BB), dim3(32, 8)>>>(xred, ln_g, ln_b);
    // 4) in_proj: xz = xn @ in_w.T   [TENSOR A/B TEST]
    gemm_inproj_t3<<<dim3(8, 36), 256>>>();
    // 5) causal conv1d + silu -> scan-ordered xm
    conv1d_k<<<dim3(LL / CCT, BB, 4), 512>>>(conv_w, conv_b);
    // 6) xproj per (dir,b), permuted weights -> B/C interleaved output
    gemm_xproj<<<dim3(18, 8), 192>>>();
    // 7) dt = softplus(...)
    dt_k<<<dim3(LL / DTT, BB, 4), 512>>>(dt_b);
    // 8) selective scan
    scan_k<<<512, 128>>>(A_log, Dp);
    // 9) gather directions + silu(z) gate
    ysum_k<<<(BL * DI + 255) / 256, 256>>>();
    // 10) feat_global = 0.25 * (out_w @ ysum) + x
    gemm128<3, true><<<dim3(36, 2, BB), 256>>>(out_w, ysum, featglob, 256, 2304, 512,
        0, (long long)LL * DI, (long long)CC * HWW, (const float*)0, (const float*)0,
        xred, (long long)CC * HWW);
    // 11) p = relu(bn1(proj_w @ x))
    gemm128<1, false><<<dim3(36, 2, BB), 256>>>(proj_w, xred, p, 256, 2304, 256,
        0, (long long)CC * HWW, (long long)CC * HWW, bn1_g, bn1_b, (const float*)0, 0);
    // 12) depthwise h+v fused
    dwconv_k<<<(BB * CC * HWW + 255) / 256, 256>>>(p, dwh_w, dwv_w,
                                                   bnh_g, bnh_b, bnv_g, bnv_b, hv);
    // 13) feat_local = fus_w @ (h+v) + fus_b
    gemm128<2, false><<<dim3(36, 2, BB), 256>>>(fus_w, hv, featloc, 256, 2304, 256,
        0, (long long)CC * HWW, (long long)CC * HWW, (const float*)0, fus_b, (const float*)0, 0);
    // 14-16) SE head + final combine
    mean_k<<<dim3(CC, BB), 256>>>();
    fc_k<<<BB, 256>>>(fc1_w, fc2_w);
    final_k<<<(BB * CC * HWW + 255) / 256, 256>>>((float*)d_out);
}

// round 14
// speedup vs baseline: 1.5707x; 1.0251x over previous
#include <cuda_runtime.h>
#include <cuda_bf16.h>
#include <stdint.h>
#include <math.h>

#define BB  2
#define CIN 512
#define CC  256
#define HH  48
#define WW  48
#define HWW 2304
#define LL  2304
#define DI  512
#define BL  (BB*LL)
#define BNF 0.9999950000374997f

typedef __nv_bfloat16 bf16;

// ------------------------- static scratch (no allocs) -------------------------
__device__ __align__(256) float g_xred[BL*CC];        // token-major
__device__ __align__(256) float g_p[BL*CC];
__device__ __align__(256) float g_featloc[BL*CC];
__device__ __align__(256) float g_featglob[BL*CC];
__device__ __align__(256) float g_xz[BL*2*DI];
__device__ __align__(256) float g_xm[4*BL*DI];
__device__ __align__(256) float g_projm[4*BL*48];
__device__ __align__(256) float g_dtb[4*BL*DI];
__device__ __align__(256) bf16  g_y[4*BL*DI];
// bf16 split activations
__device__ __align__(256) bf16 g_xthi[BL*CIN],  g_xtlo[BL*CIN];
__device__ __align__(256) bf16 g_xrhi[BL*CC],   g_xrlo[BL*CC];
__device__ __align__(256) bf16 g_xnhi[BL*CC],   g_xnlo[BL*CC];
__device__ __align__(256) bf16 g_hvhi[BL*CC],   g_hvlo[BL*CC];
__device__ __align__(256) bf16 g_yshi[BL*DI],   g_yslo[BL*DI];
// bf16 split weights
__device__ __align__(256) bf16 g_rwhi[CC*CIN],  g_rwlo[CC*CIN];
__device__ __align__(256) bf16 g_pwhi[CC*CC],   g_pwlo[CC*CC];
__device__ __align__(256) bf16 g_fwhi[CC*CC],   g_fwlo[CC*CC];
__device__ __align__(256) bf16 g_iwhi[2*DI*CC], g_iwlo[2*DI*CC];
__device__ __align__(256) bf16 g_owhi[CC*DI],   g_owlo[CC*DI];
// misc
__device__ __align__(256) float g_dtwT[16*DI];
__device__ __align__(256) float g_xpw[48*DI];
__device__ __align__(256) int   g_map[4*LL];
__device__ __align__(256) float g_msum[BB*36*CC];
__device__ __align__(256) float g_sv[BB*CC];
__device__ __align__(256) float g_wv[BB*2*CC];

__device__ __forceinline__ int seq_map(int dir, int t) {
    if (dir == 0) return t;
    if (dir == 1) return LL - 1 - t;
    int u = (dir == 2) ? t : (LL - 1 - t);
    int h = u % HH, w = u / HH;
    return h * WW + w;
}
__device__ __forceinline__ float silu_f(float x) { return x / (1.f + __expf(-x)); }
__device__ __forceinline__ void split_bf(float v, bf16& h, bf16& l) {
    h = __float2bfloat16(v);
    l = __float2bfloat16(v - __bfloat162float(h));
}

// ------------------ one-time prep ---------------------------------------------
__global__ void init_misc_k(const float* __restrict__ dtw, const float* __restrict__ xpw,
                            const float* __restrict__ rw, const float* __restrict__ pw,
                            const float* __restrict__ fw, const float* __restrict__ iw,
                            const float* __restrict__ ow)
{
    int i = blockIdx.x * 256 + threadIdx.x;
    if (i < 16 * DI) {
        int dd = i >> 4, r = i & 15;
        g_dtwT[r * DI + dd] = dtw[i];
    }
    if (i < 4 * LL) g_map[i] = seq_map(i / LL, i % LL);
    if (i < 48 * DI) {
        int j = i >> 9, k = i & 511;
        int src = (j < 16) ? j
                : (((j - 16) & 1) ? 32 + ((j - 16) >> 1) : 16 + ((j - 16) >> 1));
        g_xpw[i] = xpw[src * DI + k];
    }
    int o = i;
    if (o < CC*CIN) { split_bf(rw[o], g_rwhi[o], g_rwlo[o]); return; }
    o -= CC*CIN;
    if (o < CC*CC)  { split_bf(pw[o], g_pwhi[o], g_pwlo[o]); return; }
    o -= CC*CC;
    if (o < CC*CC)  { split_bf(fw[o], g_fwhi[o], g_fwlo[o]); return; }
    o -= CC*CC;
    if (o < 2*DI*CC){ split_bf(iw[o], g_iwhi[o], g_iwlo[o]); return; }
    o -= 2*DI*CC;
    if (o < CC*DI)  { split_bf(ow[o], g_owhi[o], g_owlo[o]); return; }
}

// ---------- input transpose: x[b][cin][hw] -> xT hi/lo ------------------------
__global__ void trans_in_k(const float* __restrict__ x)
{
    __shared__ float tile[32][33];
    int b = blockIdx.z;
    int l0 = blockIdx.x * 32, c0 = blockIdx.y * 32;
    int tx = threadIdx.x, ty = threadIdx.y;      // (32,8)
#pragma unroll
    for (int i = 0; i < 4; i++)
        tile[ty + i*8][tx] = x[((long long)b*CIN + c0 + ty + i*8) * HWW + l0 + tx];
    __syncthreads();
#pragma unroll
    for (int i = 0; i < 4; i++) {
        long long o = ((long long)b*HWW + l0 + ty + i*8) * CIN + c0 + tx;
        bf16 h, l;
        split_bf(tile[tx][ty + i*8], h, l);
        g_xthi[o] = h; g_xtlo[o] = l;
    }
}

// ======================= mma primitive ========================================
#define ASTR 40
__device__ __forceinline__ void mma16816(float* d, uint32_t a0, uint32_t a1,
                                         uint32_t a2, uint32_t a3,
                                         uint32_t b0, uint32_t b1)
{
    asm volatile(
        "mma.sync.aligned.m16n8k16.row.col.f32.bf16.bf16.f32 "
        "{%0,%1,%2,%3}, {%4,%5,%6,%7}, {%8,%9}, {%0,%1,%2,%3};\n"
        : "+f"(d[0]), "+f"(d[1]), "+f"(d[2]), "+f"(d[3])
        : "r"(a0), "r"(a1), "r"(a2), "r"(a3), "r"(b0), "r"(b1));
}

// ---------------- big 128x128 tensor GEMM (in_proj, validated R11) ------------
__global__ void __launch_bounds__(256) gemm_inproj_t3()
{
    __shared__ bf16 As[128 * ASTR];
    __shared__ bf16 Bs[128 * ASTR];
    const int K = CC;
    const int N = 2 * DI;
    int tid = threadIdx.x;
    int warp = tid >> 5, lane = tid & 31;
    int gID = lane >> 2, tig = lane & 3;
    int wm = (warp >> 2) * 64, wn = (warp & 3) * 32;
    int m0 = blockIdx.y * 128, n0 = blockIdx.x * 128;

    int u0 = tid, u1 = tid + 256;
    int ar0 = u0 >> 2, ac0 = (u0 & 3) * 8;
    int ar1 = u1 >> 2, ac1 = (u1 & 3) * 8;

    uint4 ra[2], rb[2];
    ra[0] = *(const uint4*)(g_xnhi + (long long)(m0 + ar0) * K + ac0);
    ra[1] = *(const uint4*)(g_xnhi + (long long)(m0 + ar1) * K + ac1);
    rb[0] = *(const uint4*)(g_iwhi + (long long)(n0 + ar0) * K + ac0);
    rb[1] = *(const uint4*)(g_iwhi + (long long)(n0 + ar1) * K + ac1);

    float acc[4][4][4] = {};
    const int G = 24;

    for (int g = 0; g < G; g++) {
        *(uint4*)&As[ar0 * ASTR + ac0] = ra[0];
        *(uint4*)&As[ar1 * ASTR + ac1] = ra[1];
        *(uint4*)&Bs[ar0 * ASTR + ac0] = rb[0];
        *(uint4*)&Bs[ar1 * ASTR + ac1] = rb[1];
        __syncthreads();
        int gn = g + 1;
        if (gn < G) {
            int pass = gn >> 3;
            int kk = (gn & 7) * 32;
            const bf16* Ag = (pass == 1) ? g_xnlo : g_xnhi;
            const bf16* Bg = (pass == 2) ? g_iwlo : g_iwhi;
            ra[0] = *(const uint4*)(Ag + (long long)(m0 + ar0) * K + kk + ac0);
            ra[1] = *(const uint4*)(Ag + (long long)(m0 + ar1) * K + kk + ac1);
            rb[0] = *(const uint4*)(Bg + (long long)(n0 + ar0) * K + kk + ac0);
            rb[1] = *(const uint4*)(Bg + (long long)(n0 + ar1) * K + kk + ac1);
        }
#pragma unroll
        for (int ks = 0; ks < 32; ks += 16) {
            uint32_t af[4][4], bfr[4][2];
#pragma unroll
            for (int mi = 0; mi < 4; mi++) {
                int r = wm + mi*16 + gID;
                af[mi][0] = *(const uint32_t*)&As[r * ASTR + ks + 2*tig];
                af[mi][1] = *(const uint32_t*)&As[(r+8) * ASTR + ks + 2*tig];
                af[mi][2] = *(const uint32_t*)&As[r * ASTR + ks + 2*tig + 8];
                af[mi][3] = *(const uint32_t*)&As[(r+8) * ASTR + ks + 2*tig + 8];
            }
#pragma unroll
            for (int nj = 0; nj < 4; nj++) {
                int r = wn + nj*8 + gID;
                bfr[nj][0] = *(const uint32_t*)&Bs[r * ASTR + ks + 2*tig];
                bfr[nj][1] = *(const uint32_t*)&Bs[r * ASTR + ks + 2*tig + 8];
            }
#pragma unroll
            for (int mi = 0; mi < 4; mi++)
#pragma unroll
                for (int nj = 0; nj < 4; nj++)
                    mma16816(acc[mi][nj], af[mi][0], af[mi][1], af[mi][2], af[mi][3],
                             bfr[nj][0], bfr[nj][1]);
        }
        __syncthreads();
    }

#pragma unroll
    for (int mi = 0; mi < 4; mi++)
#pragma unroll
    for (int nj = 0; nj < 4; nj++) {
        int m = m0 + wm + mi*16 + gID;
        int n = n0 + wn + nj*8 + 2*tig;
        float* a = acc[mi][nj];
#pragma unroll
        for (int half = 0; half < 2; half++) {
            int mm = m + half * 8;
            *(float2*)&g_xz[(long long)mm * N + n] = make_float2(a[half*2], a[half*2+1]);
        }
    }
}

// ---------------- small 64x64 tensor GEMM (4 warps, warp 32x32) ---------------
// MODE: 0 plain; 1 BN+ReLU + hi/lo; 2 BN+ReLU; 3 +bias; 4 0.25*+extra
template<int MODE>
__global__ void __launch_bounds__(128) gemm_t3s(
    const bf16* __restrict__ Ahi, const bf16* __restrict__ Alo,
    const bf16* __restrict__ Bhi, const bf16* __restrict__ Blo,
    float* __restrict__ outf, bf16* __restrict__ ohi, bf16* __restrict__ olo,
    int N, int K,
    const float* __restrict__ sc, const float* __restrict__ bi,
    const float* __restrict__ extra)
{
    __shared__ bf16 As[64 * ASTR];
    __shared__ bf16 Bs[64 * ASTR];
    int tid = threadIdx.x;
    int warp = tid >> 5, lane = tid & 31;
    int gID = lane >> 2, tig = lane & 3;
    int wm = (warp >> 1) * 32, wn = (warp & 1) * 32;
    int m0 = blockIdx.y * 64, n0 = blockIdx.x * 64;

    int ar = tid >> 2;              // 0..31
    int ac = (tid & 3) * 8;

    int K32 = K >> 5;
    int G = 3 * K32;

    uint4 ra[2], rb[2];
    ra[0] = *(const uint4*)(Ahi + (long long)(m0 + ar) * K + ac);
    ra[1] = *(const uint4*)(Ahi + (long long)(m0 + ar + 32) * K + ac);
    rb[0] = *(const uint4*)(Bhi + (long long)(n0 + ar) * K + ac);
    rb[1] = *(const uint4*)(Bhi + (long long)(n0 + ar + 32) * K + ac);

    float acc[2][4][4] = {};

    for (int g = 0; g < G; g++) {
        *(uint4*)&As[ar * ASTR + ac] = ra[0];
        *(uint4*)&As[(ar + 32) * ASTR + ac] = ra[1];
        *(uint4*)&Bs[ar * ASTR + ac] = rb[0];
        *(uint4*)&Bs[(ar + 32) * ASTR + ac] = rb[1];
        __syncthreads();
        int gn = g + 1;
        if (gn < G) {
            int pass = gn / K32;
            int kk = (gn - pass * K32) * 32;
            const bf16* Ag = (pass == 1) ? Alo : Ahi;
            const bf16* Bg = (pass == 2) ? Blo : Bhi;
            ra[0] = *(const uint4*)(Ag + (long long)(m0 + ar) * K + kk + ac);
            ra[1] = *(const uint4*)(Ag + (long long)(m0 + ar + 32) * K + kk + ac);
            rb[0] = *(const uint4*)(Bg + (long long)(n0 + ar) * K + kk + ac);
            rb[1] = *(const uint4*)(Bg + (long long)(n0 + ar + 32) * K + kk + ac);
        }
#pragma unroll
        for (int ks = 0; ks < 32; ks += 16) {
            uint32_t af[2][4], bfr[4][2];
#pragma unroll
            for (int mi = 0; mi < 2; mi++) {
                int r = wm + mi*16 + gID;
                af[mi][0] = *(const uint32_t*)&As[r * ASTR + ks + 2*tig];
                af[mi][1] = *(const uint32_t*)&As[(r+8) * ASTR + ks + 2*tig];
                af[mi][2] = *(const uint32_t*)&As[r * ASTR + ks + 2*tig + 8];
                af[mi][3] = *(const uint32_t*)&As[(r+8) * ASTR + ks + 2*tig + 8];
            }
#pragma unroll
            for (int nj = 0; nj < 4; nj++) {
                int r = wn + nj*8 + gID;
                bfr[nj][0] = *(const uint32_t*)&Bs[r * ASTR + ks + 2*tig];
                bfr[nj][1] = *(const uint32_t*)&Bs[r * ASTR + ks + 2*tig + 8];
            }
#pragma unroll
            for (int mi = 0; mi < 2; mi++)
#pragma unroll
                for (int nj = 0; nj < 4; nj++)
                    mma16816(acc[mi][nj], af[mi][0], af[mi][1], af[mi][2], af[mi][3],
                             bfr[nj][0], bfr[nj][1]);
        }
        __syncthreads();
    }

#pragma unroll
    for (int mi = 0; mi < 2; mi++)
#pragma unroll
    for (int nj = 0; nj < 4; nj++) {
        int m = m0 + wm + mi*16 + gID;
        int n = n0 + wn + nj*8 + 2*tig;
        float* a = acc[mi][nj];
#pragma unroll
        for (int half = 0; half < 2; half++) {
            int mm = m + half * 8;
            float v0 = a[half*2 + 0], v1 = a[half*2 + 1];
            if (MODE == 1 || MODE == 2) {
                v0 = fmaxf(fmaf(v0, sc[n] * BNF, bi[n]), 0.f);
                v1 = fmaxf(fmaf(v1, sc[n+1] * BNF, bi[n+1]), 0.f);
            } else if (MODE == 3) {
                v0 += bi[n]; v1 += bi[n+1];
            } else if (MODE == 4) {
                const float2 e = *(const float2*)&extra[(long long)mm * N + n];
                v0 = fmaf(v0, 0.25f, e.x);
                v1 = fmaf(v1, 0.25f, e.y);
            }
            long long o = (long long)mm * N + n;
            *(float2*)&outf[o] = make_float2(v0, v1);
            if (MODE == 1) {
                bf16 h0, l0b, h1, l1b;
                split_bf(v0, h0, l0b);
                split_bf(v1, h1, l1b);
                __nv_bfloat162 hh; hh.x = h0; hh.y = h1;
                __nv_bfloat162 ll; ll.x = l0b; ll.y = l1b;
                *(__nv_bfloat162*)&ohi[o] = hh;
                *(__nv_bfloat162*)&olo[o] = ll;
            }
        }
    }
}

// ---------------- xproj (SIMT): proj = xm @ Wperm.T ---------------------------
__global__ void __launch_bounds__(192) gemm_xproj()
{
    __shared__ float As[16][132];
    __shared__ float Bs[16][52];
    int tid = threadIdx.x;
    int zb = blockIdx.y;
    int m0 = blockIdx.x * 128;
    const float* Ab = g_xm + (long long)zb * LL * DI;
    const float* aptr = Ab + (long long)(m0 + tid) * DI;
    int bn = tid >> 2, bk = (tid & 3) * 4;
    const float* bptr = g_xpw + bn * DI + bk;
    int ty = tid / 12, txx = tid % 12;

    float4 pa[4], pbv;
    if (tid < 128) {
#pragma unroll
        for (int j = 0; j < 4; j++) pa[j] = ((const float4*)aptr)[j];
    }
    pbv = *(const float4*)bptr;

    float acc[8][4] = {};
    for (int k0 = 0; k0 < DI; k0 += 16) {
        if (tid < 128) {
#pragma unroll
            for (int j = 0; j < 4; j++) {
                As[j*4+0][tid] = pa[j].x;
                As[j*4+1][tid] = pa[j].y;
                As[j*4+2][tid] = pa[j].z;
                As[j*4+3][tid] = pa[j].w;
            }
        }
        Bs[bk+0][bn] = pbv.x; Bs[bk+1][bn] = pbv.y;
        Bs[bk+2][bn] = pbv.z; Bs[bk+3][bn] = pbv.w;
        __syncthreads();
        if (k0 + 16 < DI) {
            if (tid < 128) {
                const float* an = aptr + k0 + 16;
#pragma unroll
                for (int j = 0; j < 4; j++) pa[j] = ((const float4*)an)[j];
            }
            pbv = *(const float4*)(bptr + k0 + 16);
        }
#pragma unroll
        for (int k = 0; k < 16; k++) {
            float4 a0 = *(const float4*)&As[k][ty*8];
            float4 a1 = *(const float4*)&As[k][ty*8+4];
            float4 b4 = *(const float4*)&Bs[k][txx*4];
            float a[8] = {a0.x,a0.y,a0.z,a0.w,a1.x,a1.y,a1.z,a1.w};
            float bv[4] = {b4.x,b4.y,b4.z,b4.w};
#pragma unroll
            for (int i = 0; i < 8; i++)
#pragma unroll
                for (int j = 0; j < 4; j++)
                    acc[i][j] = fmaf(a[i], bv[j], acc[i][j]);
        }
        __syncthreads();
    }
#pragma unroll
    for (int i = 0; i < 8; i++) {
        int m = m0 + ty*8 + i;
        *(float4*)(g_projm + ((long long)zb * LL + m) * 48 + txx*4) =
            make_float4(acc[i][0], acc[i][1], acc[i][2], acc[i][3]);
    }
}

// ------- layernorm over c (rows contiguous), emits xn hi/lo -------------------
__global__ void __launch_bounds__(256) ln_k(const float* __restrict__ lng,
                                            const float* __restrict__ lnb)
{
    int w = threadIdx.x >> 5, lane = threadIdx.x & 31;
    int tok = blockIdx.x * 8 + w;
    const float* xp = g_xred + (long long)tok * CC;
    float4 v0 = *(const float4*)(xp + lane*4);
    float4 v1 = *(const float4*)(xp + 128 + lane*4);
    float s = v0.x+v0.y+v0.z+v0.w + v1.x+v1.y+v1.z+v1.w;
    float ss = v0.x*v0.x+v0.y*v0.y+v0.z*v0.z+v0.w*v0.w
             + v1.x*v1.x+v1.y*v1.y+v1.z*v1.z+v1.w*v1.w;
#pragma unroll
    for (int o = 16; o; o >>= 1) {
        s  += __shfl_xor_sync(0xffffffffu, s, o);
        ss += __shfl_xor_sync(0xffffffffu, ss, o);
    }
    float mu = s * (1.f/CC);
    float rstd = rsqrtf(ss * (1.f/CC) - mu*mu + 1e-5f);
    float4 g0 = *(const float4*)(lng + lane*4);
    float4 g1 = *(const float4*)(lng + 128 + lane*4);
    float4 b0 = *(const float4*)(lnb + lane*4);
    float4 b1 = *(const float4*)(lnb + 128 + lane*4);
    float vals[8] = {v0.x,v0.y,v0.z,v0.w, v1.x,v1.y,v1.z,v1.w};
    float gs[8] = {g0.x,g0.y,g0.z,g0.w, g1.x,g1.y,g1.z,g1.w};
    float bs[8] = {b0.x,b0.y,b0.z,b0.w, b1.x,b1.y,b1.z,b1.w};
    bf16 hi[8], lo[8];
#pragma unroll
    for (int i = 0; i < 8; i++) {
        float xn = (vals[i] - mu) * rstd * gs[i] + bs[i];
        split_bf(xn, hi[i], lo[i]);
    }
    long long base = (long long)tok * CC;
    *(uint2*)&g_xnhi[base + lane*4] = *(uint2*)&hi[0];
    *(uint2*)&g_xnhi[base + 128 + lane*4] = *(uint2*)&hi[4];
    *(uint2*)&g_xnlo[base + lane*4] = *(uint2*)&lo[0];
    *(uint2*)&g_xnlo[base + 128 + lane*4] = *(uint2*)&lo[4];
}

// -------- causal depthwise conv1d + silu (scan order) -------------------------
#define CCT 64
__global__ void __launch_bounds__(512) conv1d_k(const float* __restrict__ cw,
                                                const float* __restrict__ cb)
{
    __shared__ int sl[CCT + 3];
    int d = threadIdx.x;
    int t0 = blockIdx.x * CCT;
    int b = blockIdx.y;
    int dir = blockIdx.z;
    if (d < CCT + 3) {
        int tt = t0 - 3 + d;
        sl[d] = (tt >= 0) ? g_map[dir * LL + tt] : 0;
    }
    __syncthreads();
    float w0 = cw[d*4+0], w1 = cw[d*4+1], w2 = cw[d*4+2], w3 = cw[d*4+3];
    float bias = cb[d];
    const float* xzb = g_xz + (long long)b * LL * 1024 + d;
    float x0 = 0.f, x1 = 0.f, x2 = 0.f;
    if (t0 > 0) {
        x0 = xzb[(long long)sl[0] * 1024];
        x1 = xzb[(long long)sl[1] * 1024];
        x2 = xzb[(long long)sl[2] * 1024];
    }
    float xn = xzb[(long long)sl[3] * 1024];
    float* yo = &g_xm[(((long long)dir * BB + b) * LL + t0) * DI + d];
    for (int i = 0; i < CCT; i++) {
        float xnn = (i + 1 < CCT) ? xzb[(long long)sl[i + 4] * 1024] : 0.f;
        float s = bias + w0*x0 + w1*x1 + w2*x2 + w3*xn;
        yo[(long long)i * DI] = silu_f(s);
        x0 = x1; x1 = x2; x2 = xn; xn = xnn;
    }
}

// ---------- dt = softplus(proj[:,:16] @ dt_w.T + dt_b) ------------------------
#define DTT 16
__global__ void __launch_bounds__(512) dt_k(const float* __restrict__ dtbias)
{
    __shared__ float pr[DTT][16];
    int d = threadIdx.x;
    int t0 = blockIdx.x * DTT;
    int b = blockIdx.y, dir = blockIdx.z;
    long long row0 = ((long long)dir * BB + b) * LL + t0;
    if (d < DTT * 16) {
        int ti = d >> 4, r = d & 15;
        pr[ti][r] = g_projm[(row0 + ti) * 48 + r];
    }
    float wreg[16];
#pragma unroll
    for (int r = 0; r < 16; r++) wreg[r] = g_dtwT[r * DI + d];
    float bias = dtbias[d];
    __syncthreads();
    float* out = &g_dtb[row0 * DI + d];
#pragma unroll 4
    for (int t = 0; t < DTT; t++) {
        float acc = bias;
#pragma unroll
        for (int r = 0; r < 16; r++) acc = fmaf(pr[t][r], wreg[r], acc);
        float dt = (acc > 15.f) ? acc : log1pf(expf(acc));
        out[(long long)t * DI] = dt;
    }
}

// ------------------------- selective scan (PF=8, float2 BC) -------------------
__global__ void __launch_bounds__(128) scan_k(const float* __restrict__ A_log,
                                              const float* __restrict__ Dp)
{
    int tid = threadIdx.x;
    int lane = tid & 31;
    int gwarp = blockIdx.x * 4 + (tid >> 5);
    int dir = gwarp >> 9;
    int b = (gwarp >> 8) & 1;
    int d = ((gwarp & 255) << 1) | (lane >> 4);
    int s = lane & 15;

    float Av = -expf(A_log[d * 16 + s]);
    float Dv = Dp[d];
    long long dbase = ((long long)dir * BB + b) * LL;
    const float* pdt = g_dtb + dbase * DI + d;
    const float* pxm = g_xm + dbase * DI + d;
    const float2* pbc = reinterpret_cast<const float2*>(g_projm) + dbase * 24 + 8 + s;
    bf16* py = g_y + dbase * DI + d;

    const int PF = 8;
    float f_dt[PF], f_x[PF];
    float2 f_bc[PF];
#pragma unroll
    for (int i = 0; i < PF; i++) {
        f_dt[i] = pdt[i * DI];
        f_x[i]  = pxm[i * DI];
        f_bc[i] = pbc[i * 24];
    }
    const float* qdt = pdt + PF * DI;
    const float* qxm = pxm + PF * DI;
    const float2* qbc = pbc + PF * 24;

    float h = 0.f;
    for (int t0 = 0; t0 < LL; t0 += PF) {
        bool pf = (t0 + PF < LL);
#pragma unroll
        for (int i = 0; i < PF; i++) {
            float dtv = f_dt[i], xv = f_x[i];
            float Bv = f_bc[i].x, Cv = f_bc[i].y;
            if (pf) {
                f_dt[i] = qdt[i * DI];
                f_x[i]  = qxm[i * DI];
                f_bc[i] = qbc[i * 24];
            }
            float dA = __expf(dtv * Av);
            h = fmaf(dA, h, dtv * xv * Bv);
            float part = h * Cv;
            part += __shfl_xor_sync(0xffffffffu, part, 1);
            part += __shfl_xor_sync(0xffffffffu, part, 2);
            part += __shfl_xor_sync(0xffffffffu, part, 4);
            part += __shfl_xor_sync(0xffffffffu, part, 8);
            if (s == 0) py[i * DI] = __float2bfloat16(fmaf(Dv, xv, part));
        }
        qdt += PF * DI; qxm += PF * DI; qbc += PF * 24; py += PF * DI;
    }
}

// ----- gather 4 dirs to natural order, silu(z) gate, emit ysum hi/lo ----------
__global__ void ysum_k()
{
    long long i = (long long)blockIdx.x * blockDim.x + threadIdx.x;
    if (i >= (long long)BL * DI) return;
    int d = (int)(i & (DI - 1));
    int l = (int)((i / DI) % LL);
    int b = (int)(i / ((long long)LL * DI));
    int t2 = (l % WW) * HH + l / WW;
    const long long st = (long long)BB * LL * DI;
    long long bb = (long long)b * LL * DI;
    float y = __bfloat162float(g_y[bb + (long long)l * DI + d])
            + __bfloat162float(g_y[st + bb + (long long)(LL - 1 - l) * DI + d])
            + __bfloat162float(g_y[2 * st + bb + (long long)t2 * DI + d])
            + __bfloat162float(g_y[3 * st + bb + (long long)(LL - 1 - t2) * DI + d]);
    float z = g_xz[((long long)b * LL + l) * 1024 + DI + d];
    float v = y * silu_f(z);
    bf16 h, lo;
    split_bf(v, h, lo);
    long long o = ((long long)b * LL + l) * DI + d;
    g_yshi[o] = h; g_yslo[o] = lo;
}

// ------------- depthwise 1x7 + 7x1, smem-tiled token-major --------------------
// block: 8x8 spatial x 32 channels, halo 3. grid (36, 8, BB), 256 thr.
__global__ void __launch_bounds__(256) dwconv_tile_k(
    const float* __restrict__ wh, const float* __restrict__ wv,
    const float* __restrict__ hg, const float* __restrict__ hb,
    const float* __restrict__ vg, const float* __restrict__ vb)
{
    __shared__ float sm[14*14*32];
    int b = blockIdx.z;
    int c0 = blockIdx.y * 32;
    int tx0 = (blockIdx.x % 6) * 8, ty0 = (blockIdx.x / 6) * 8;
    int tid = threadIdx.x;

    for (int e = tid; e < 14*14*32; e += 256) {
        int c = e & 31;
        int rest = e >> 5;
        int xx = rest % 14, yy = rest / 14;
        int y = ty0 + yy - 3, x = tx0 + xx - 3;
        float v = 0.f;
        if (y >= 0 && y < HH && x >= 0 && x < WW)
            v = g_p[((long long)b * HWW + y * WW + x) * CC + c0 + c];
        sm[e] = v;
    }
    __syncthreads();

    int c = tid & 31, sy = tid >> 5;          // sy 0..7
    int cc = c0 + c;
    float whr[7], wvr[7];
#pragma unroll
    for (int j = 0; j < 7; j++) { whr[j] = wh[cc*7 + j]; wvr[j] = wv[cc*7 + j]; }
    float hgv = hg[cc] * BNF, hbv = hb[cc];
    float vgv = vg[cc] * BNF, vbv = vb[cc];

#pragma unroll
    for (int sx = 0; sx < 8; sx++) {
        float sh = 0.f, sv = 0.f;
#pragma unroll
        for (int j = 0; j < 7; j++) {
            sh = fmaf(sm[((sy+3)*14 + sx+j)*32 + c], whr[j], sh);
            sv = fmaf(sm[((sy+j)*14 + sx+3)*32 + c], wvr[j], sv);
        }
        float rh = fmaxf(fmaf(sh, hgv, hbv), 0.f);
        float rv = fmaxf(fmaf(sv, vgv, vbv), 0.f);
        bf16 h, lo;
        split_bf(rh + rv, h, lo);
        long long o = ((long long)b * HWW + (ty0+sy) * WW + tx0 + sx) * CC + cc;
        g_hvhi[o] = h; g_hvlo[o] = lo;
    }
}

// ------------------------- SE head (token-major) ------------------------------
__global__ void mean1_k()
{
    int blk = blockIdx.x, b = blockIdx.y, c = threadIdx.x;
    float s = 0.f;
    for (int i = 0; i < 64; i++) {
        long long idx = ((long long)b * HWW + blk * 64 + i) * CC + c;
        s += g_featloc[idx] + g_featglob[idx];
    }
    g_msum[(b * 36 + blk) * CC + c] = s;
}
__global__ void mean2_k()
{
    int b = blockIdx.x, c = threadIdx.x;
    float s = 0.f;
    for (int i = 0; i < 36; i++) s += g_msum[(b * 36 + i) * CC + c];
    g_sv[b * CC + c] = s / (float)HWW;
}

__global__ void fc_k(const float* __restrict__ fc1, const float* __restrict__ fc2)
{
    int b = blockIdx.x;
    __shared__ float ss[CC], tt[16];
    int tid = threadIdx.x;
    ss[tid] = g_sv[b * CC + tid];
    __syncthreads();
    if (tid < 16) {
        float a = 0.f;
        for (int c = 0; c < CC; c++) a += ss[c] * fc1[tid * CC + c];
        tt[tid] = fmaxf(a, 0.f);
    }
    __syncthreads();
    float z0 = 0.f, z1 = 0.f;
#pragma unroll
    for (int m = 0; m < 16; m++) {
        z0 += tt[m] * fc2[tid * 16 + m];
        z1 += tt[m] * fc2[(CC + tid) * 16 + m];
    }
    float mx = fmaxf(z0, z1);
    float e0 = expf(z0 - mx), e1 = expf(z1 - mx);
    float w0 = e0 / (e0 + e1);
    g_wv[b * 2 * CC + tid] = w0;
    g_wv[b * 2 * CC + CC + tid] = 1.f - w0;
}

// ---- final combine + transpose [l][c] -> out[b][c][hw] -----------------------
__global__ void final_trans_k(float* __restrict__ out)
{
    __shared__ float tile[32][33];
    int b = blockIdx.z;
    int l0 = blockIdx.x * 32, c0 = blockIdx.y * 32;
    int tx = threadIdx.x, ty = threadIdx.y;   // (32,8)
    float w0 = g_wv[b * 2 * CC + c0 + tx];
    float w1 = g_wv[b * 2 * CC + CC + c0 + tx];
#pragma unroll
    for (int i = 0; i < 4; i++) {
        long long idx = ((long long)b * HWW + l0 + ty + i*8) * CC + c0 + tx;
        tile[ty + i*8][tx] = w0 * g_featloc[idx] + w1 * g_featglob[idx];
    }
    __syncthreads();
#pragma unroll
    for (int i = 0; i < 4; i++)
        out[((long long)b * CC + c0 + ty + i*8) * HWW + l0 + tx] = tile[tx][ty + i*8];
}

// ------------------------- launch ---------------------------------------------
extern "C" void kernel_launch(void* const* d_in, const int* in_sizes, int n_in,
                              void* d_out, int out_size)
{
    const float* x        = (const float*)d_in[0];
    const float* reduce_w = (const float*)d_in[1];
    const float* bn0_g    = (const float*)d_in[2];
    const float* bn0_b    = (const float*)d_in[3];
    const float* proj_w   = (const float*)d_in[4];
    const float* bn1_g    = (const float*)d_in[5];
    const float* bn1_b    = (const float*)d_in[6];
    const float* dwh_w    = (const float*)d_in[7];
    const float* bnh_g    = (const float*)d_in[8];
    const float* bnh_b    = (const float*)d_in[9];
    const float* dwv_w    = (const float*)d_in[10];
    const float* bnv_g    = (const float*)d_in[11];
    const float* bnv_b    = (const float*)d_in[12];
    const float* fus_w    = (const float*)d_in[13];
    const float* fus_b    = (const float*)d_in[14];
    const float* ln_g     = (const float*)d_in[15];
    const float* ln_b     = (const float*)d_in[16];
    const float* in_w     = (const float*)d_in[17];
    const float* conv_w   = (const float*)d_in[18];
    const float* conv_b   = (const float*)d_in[19];
    const float* xproj_w  = (const float*)d_in[20];
    const float* dt_w     = (const float*)d_in[21];
    const float* dt_b     = (const float*)d_in[22];
    const float* A_log    = (const float*)d_in[23];
    const float* Dp       = (const float*)d_in[24];
    const float* out_w    = (const float*)d_in[25];
    const float* fc1_w    = (const float*)d_in[26];
    const float* fc2_w    = (const float*)d_in[27];

    bf16 *xthi, *xtlo, *rwhi, *rwlo, *pwhi, *pwlo, *fwhi, *fwlo, *owhi, *owlo,
         *xrhi, *xrlo, *hvhi, *hvlo, *yshi, *yslo;
    float *xred, *p, *featloc, *featglob;
    cudaGetSymbolAddress((void**)&xthi, g_xthi);  cudaGetSymbolAddress((void**)&xtlo, g_xtlo);
    cudaGetSymbolAddress((void**)&rwhi, g_rwhi);  cudaGetSymbolAddress((void**)&rwlo, g_rwlo);
    cudaGetSymbolAddress((void**)&pwhi, g_pwhi);  cudaGetSymbolAddress((void**)&pwlo, g_pwlo);
    cudaGetSymbolAddress((void**)&fwhi, g_fwhi);  cudaGetSymbolAddress((void**)&fwlo, g_fwlo);
    cudaGetSymbolAddress((void**)&owhi, g_owhi);  cudaGetSymbolAddress((void**)&owlo, g_owlo);
    cudaGetSymbolAddress((void**)&xrhi, g_xrhi);  cudaGetSymbolAddress((void**)&xrlo, g_xrlo);
    cudaGetSymbolAddress((void**)&hvhi, g_hvhi);  cudaGetSymbolAddress((void**)&hvlo, g_hvlo);
    cudaGetSymbolAddress((void**)&yshi, g_yshi);  cudaGetSymbolAddress((void**)&yslo, g_yslo);
    cudaGetSymbolAddress((void**)&xred, g_xred);
    cudaGetSymbolAddress((void**)&p, g_p);
    cudaGetSymbolAddress((void**)&featloc, g_featloc);
    cudaGetSymbolAddress((void**)&featglob, g_featglob);

    // 0) one-time prep
    init_misc_k<<<2560, 256>>>(dt_w, xproj_w, reduce_w, proj_w, fus_w, in_w, out_w);
    // 1) input transpose + split
    trans_in_k<<<dim3(HWW/32, CIN/32, BB), dim3(32, 8)>>>(x);
    // 2) reduce [tensor]: xred = relu(bn0(xT @ reduce_w.T)), emits fp32 + hi/lo
    gemm_t3s<1><<<dim3(4, 72), 128>>>(xthi, xtlo, rwhi, rwlo,
        xred, xrhi, xrlo, CC, CIN, bn0_g, bn0_b, (const float*)0);
    // 3) layernorm -> xn hi/lo
    ln_k<<<BL/8, 256>>>(ln_g, ln_b);
    // 4) in_proj [tensor big]: xz = xn @ in_w.T
    gemm_inproj_t3<<<dim3(8, 36), 256>>>();
    // 5) causal conv1d + silu -> scan-ordered xm
    conv1d_k<<<dim3(LL/CCT, BB, 4), 512>>>(conv_w, conv_b);
    // 6) xproj (SIMT)
    gemm_xproj<<<dim3(18, 8), 192>>>();
    // 7) dt
    dt_k<<<dim3(LL/DTT, BB, 4), 512>>>(dt_b);
    // 8) selective scan
    scan_k<<<512, 128>>>(A_log, Dp);
    // 9) gather + gate -> ysum hi/lo
    ysum_k<<<(BL*DI + 255)/256, 256>>>();
    // 10) out_proj [tensor]: featglob = 0.25*(ysum @ out_w.T) + xred
    gemm_t3s<4><<<dim3(4, 72), 128>>>(yshi, yslo, owhi, owlo,
        featglob, (bf16*)0, (bf16*)0, CC, DI, (const float*)0, (const float*)0, xred);
    // 11) proj [tensor]: p = relu(bn1(xred @ proj_w.T))
    gemm_t3s<2><<<dim3(4, 72), 128>>>(xrhi, xrlo, pwhi, pwlo,
        p, (bf16*)0, (bf16*)0, CC, CC, bn1_g, bn1_b, (const float*)0);
    // 12) depthwise h+v (smem-tiled) -> hv hi/lo
    dwconv_tile_k<<<dim3(36, 8, BB), 256>>>(dwh_w, dwv_w, bnh_g, bnh_b, bnv_g, bnv_b);
    // 13) fus [tensor]: featloc = hv @ fus_w.T + fus_b
    gemm_t3s<3><<<dim3(4, 72), 128>>>(hvhi, hvlo, fwhi, fwlo,
        featloc, (bf16*)0, (bf16*)0, CC, CC, (const float*)0, fus_b, (const float*)0);
    // 14-16) SE head + final combine/transpose
    mean1_k<<<dim3(36, BB), 256>>>();
    mean2_k<<<BB, 256>>>();
    fc_k<<<BB, 256>>>(fc1_w, fc2_w);
    final_trans_k<<<dim3(HWW/32, CC/32, BB), dim3(32, 8)>>>((float*)d_out);
}